// round 15
// baseline (speedup 1.0000x reference)
#include <cuda_runtime.h>
#include <cuda_bf16.h>
#include <cstdint>

#define HW 4096
#define BATCH 4
#define KDIM 1152
#define NPOS 16384

// ---------------- scratch (device globals) ---------------------------------
__device__ __nv_bfloat16 g_bq[2 * BATCH * HW * 64];
__device__ __nv_bfloat16 g_bk[2 * BATCH * HW * 64];
__device__ __nv_bfloat16 g_bv[2 * BATCH * HW * 64];
__device__ float g_z[2][BATCH][HW * 64];
__device__ float g_comb[BATCH][128][HW];
__device__ float g_y[BATCH][256][HW];
__device__ float g_mean[BATCH][256];
__device__ float g_rstd[BATCH][256];
__device__ float g_psum[BATCH][32][256];
__device__ float g_psumq[BATCH][32][256];
// W' permuted: k' = (ky*3+kx)*128 + ic
__device__ __nv_bfloat16 g_Whi[256 * KDIM];
__device__ __nv_bfloat16 g_Wlo[256 * KDIM];

// ---------------- helpers ---------------------------------------------------
__device__ __forceinline__ uint32_t smem_u32(const void* p) {
    uint32_t a;
    asm("{ .reg .u64 t; cvta.to.shared.u64 t, %1; cvt.u32.u64 %0, t; }"
        : "=r"(a) : "l"(p));
    return a;
}
__device__ __forceinline__ void ldsm_x4(uint32_t& r0, uint32_t& r1,
                                        uint32_t& r2, uint32_t& r3, uint32_t a) {
    asm volatile("ldmatrix.sync.aligned.m8n8.x4.shared.b16 {%0,%1,%2,%3}, [%4];"
                 : "=r"(r0), "=r"(r1), "=r"(r2), "=r"(r3) : "r"(a));
}
__device__ __forceinline__ void ldsm_x4_t(uint32_t& r0, uint32_t& r1,
                                          uint32_t& r2, uint32_t& r3, uint32_t a) {
    asm volatile("ldmatrix.sync.aligned.m8n8.x4.trans.shared.b16 {%0,%1,%2,%3}, [%4];"
                 : "=r"(r0), "=r"(r1), "=r"(r2), "=r"(r3) : "r"(a));
}
__device__ __forceinline__ void mma16816(float d[4], const uint32_t a[4],
                                         uint32_t b0, uint32_t b1) {
    asm volatile(
        "mma.sync.aligned.m16n8k16.row.col.f32.bf16.bf16.f32 "
        "{%0,%1,%2,%3},{%4,%5,%6,%7},{%8,%9},{%0,%1,%2,%3};"
        : "+f"(d[0]), "+f"(d[1]), "+f"(d[2]), "+f"(d[3])
        : "r"(a[0]), "r"(a[1]), "r"(a[2]), "r"(a[3]), "r"(b0), "r"(b1));
}
__device__ __forceinline__ uint32_t b2u(__nv_bfloat162 v) {
    return *reinterpret_cast<uint32_t*>(&v);
}
__device__ __forceinline__ void cp_async16(uint32_t dst, const void* src) {
    asm volatile("cp.async.ca.shared.global [%0], [%1], 16;" :: "r"(dst), "l"(src));
}
#define CP_COMMIT() asm volatile("cp.async.commit_group;" ::: "memory")
#define CP_WAIT0()  asm volatile("cp.async.wait_group 0;" ::: "memory")

// ---------------- flash attention: BM=128, 4q x 2k warps, BN=128 stages ----
#define QSTR 144
#define QS_OFF 0
#define KS_OFF 18432
#define VS_OFF 55296
#define FL_SMEM 92160

__global__ __launch_bounds__(256, 2) void flash_mma_kernel(
    const __nv_bfloat16* __restrict__ bq, const __nv_bfloat16* __restrict__ bk,
    const __nv_bfloat16* __restrict__ bv, float* __restrict__ gz)
{
    extern __shared__ char smem[];
    const uint32_t smb = smem_u32(smem);
    const int tid = threadIdx.x, w = tid >> 5, lane = tid & 31;
    const int wq = w >> 1, wk = w & 1;
    const int ab = blockIdx.z * BATCH + blockIdx.y;
    const int n0 = blockIdx.x * 128;
    const __nv_bfloat16* qb = bq + (size_t)ab * HW * 64;
    const __nv_bfloat16* kb = bk + (size_t)ab * HW * 64;
    const __nv_bfloat16* vb = bv + (size_t)ab * HW * 64;
    float* zb = gz + (size_t)ab * HW * 64;

    // Q tile: 128 rows x 64 d
    {
        int r = tid >> 1, sg = (tid & 1) * 32;
        const uint4* s = (const uint4*)(qb + (size_t)(n0 + r) * 64 + sg);
        uint4* d = (uint4*)(smem + QS_OFF + r * QSTR + sg * 2);
        d[0] = s[0]; d[1] = s[1]; d[2] = s[2]; d[3] = s[3];
    }
    // K/V tile 0 (128 keys): each thread covers half a row (32 elems)
    const int kr = tid >> 1, kh = (tid & 1) * 32;
    {
        const uint4* sk = (const uint4*)(kb + (size_t)kr * 64 + kh);
        const uint4* sv = (const uint4*)(vb + (size_t)kr * 64 + kh);
        uint4* dk = (uint4*)(smem + KS_OFF + kr * QSTR + kh * 2);
        uint4* dv = (uint4*)(smem + VS_OFF + kr * QSTR + kh * 2);
#pragma unroll
        for (int e = 0; e < 4; e++) { dk[e] = sk[e]; dv[e] = sv[e]; }
    }
    __syncthreads();

    float O[2][8][4];
#pragma unroll
    for (int m = 0; m < 2; m++)
#pragma unroll
        for (int n = 0; n < 8; n++)
#pragma unroll
            for (int e = 0; e < 4; e++) O[m][n][e] = 0.f;
    float rs[2][2] = {{0.f, 0.f}, {0.f, 0.f}};

    const uint32_t aq   = (uint32_t)(((lane >> 3) & 1) * 8 + (lane & 7));
    const uint32_t acol = (uint32_t)((lane >> 4) * 8);
    const uint32_t krow = (uint32_t)(((lane >> 4) << 3) + (lane & 7));
    const uint32_t kcs  = (uint32_t)(((lane >> 3) & 1) * 8);
    const uint32_t vrow = (uint32_t)(((lane >> 3) & 1) * 8 + (lane & 7));
    const uint32_t vcs  = (uint32_t)((lane >> 4) * 8);

    for (int t = 0; t < 32; t++) {
        const int cur = t & 1;
        const uint32_t Kst = smb + KS_OFF + cur * 18432;
        const uint32_t Vst = smb + VS_OFF + cur * 18432;
        const bool pf = (t + 1 < 32);

        if (pf) {
            size_t off = ((size_t)((t + 1) * 128 + kr)) * 64 + kh;
            uint32_t dk = smb + KS_OFF + (cur ^ 1) * 18432 + kr * QSTR + kh * 2;
            uint32_t dv = smb + VS_OFF + (cur ^ 1) * 18432 + kr * QSTR + kh * 2;
#pragma unroll
            for (int e = 0; e < 4; e++) {
                cp_async16(dk + e * 16, kb + off + e * 8);
                cp_async16(dv + e * 16, vb + off + e * 8);
            }
            CP_COMMIT();
        }

#pragma unroll
        for (int sub = 0; sub < 2; sub++) {
            const uint32_t kofs = (uint32_t)(sub * 64);

            // ---- S[32 q x 32 k(this half)] ----
            float S[2][4][4];
#pragma unroll
            for (int m = 0; m < 2; m++)
#pragma unroll
                for (int n = 0; n < 4; n++)
#pragma unroll
                    for (int e = 0; e < 4; e++) S[m][n][e] = 0.f;
#pragma unroll
            for (int ks = 0; ks < 4; ks++) {
                uint32_t qa0[4], qa1[4];
                ldsm_x4(qa0[0], qa0[1], qa0[2], qa0[3],
                        smb + QS_OFF + (wq * 32 + aq) * QSTR + (ks * 16 + acol) * 2);
                ldsm_x4(qa1[0], qa1[1], qa1[2], qa1[3],
                        smb + QS_OFF + (wq * 32 + 16 + aq) * QSTR + (ks * 16 + acol) * 2);
#pragma unroll
                for (int np = 0; np < 2; np++) {
                    uint32_t b0, b1, b2, b3;
                    ldsm_x4(b0, b1, b2, b3,
                            Kst + (kofs + wk * 32 + np * 16 + krow) * QSTR
                                + (ks * 16 + kcs) * 2);
                    mma16816(S[0][np * 2],     qa0, b0, b1);
                    mma16816(S[0][np * 2 + 1], qa0, b2, b3);
                    mma16816(S[1][np * 2],     qa1, b0, b1);
                    mma16816(S[1][np * 2 + 1], qa1, b2, b3);
                }
            }

            // ---- exp + partial row sums ----
#pragma unroll
            for (int m = 0; m < 2; m++)
#pragma unroll
                for (int n = 0; n < 4; n++) {
                    S[m][n][0] = __expf(S[m][n][0]); S[m][n][1] = __expf(S[m][n][1]);
                    S[m][n][2] = __expf(S[m][n][2]); S[m][n][3] = __expf(S[m][n][3]);
                    rs[m][0] += S[m][n][0] + S[m][n][1];
                    rs[m][1] += S[m][n][2] + S[m][n][3];
                }
            uint32_t pa[2][2][4];
#pragma unroll
            for (int kt = 0; kt < 2; kt++)
#pragma unroll
                for (int m = 0; m < 2; m++) {
                    pa[kt][m][0] = b2u(__floats2bfloat162_rn(S[m][2*kt][0],   S[m][2*kt][1]));
                    pa[kt][m][1] = b2u(__floats2bfloat162_rn(S[m][2*kt][2],   S[m][2*kt][3]));
                    pa[kt][m][2] = b2u(__floats2bfloat162_rn(S[m][2*kt+1][0], S[m][2*kt+1][1]));
                    pa[kt][m][3] = b2u(__floats2bfloat162_rn(S[m][2*kt+1][2], S[m][2*kt+1][3]));
                }

            // ---- O += P.V over this key half ----
#pragma unroll
            for (int kt = 0; kt < 2; kt++)
#pragma unroll
                for (int np = 0; np < 4; np++) {
                    uint32_t b0, b1, b2, b3;
                    ldsm_x4_t(b0, b1, b2, b3,
                              Vst + (kofs + wk * 32 + kt * 16 + vrow) * QSTR
                                  + (np * 16 + vcs) * 2);
                    mma16816(O[0][np * 2],     pa[kt][0], b0, b1);
                    mma16816(O[0][np * 2 + 1], pa[kt][0], b2, b3);
                    mma16816(O[1][np * 2],     pa[kt][1], b0, b1);
                    mma16816(O[1][np * 2 + 1], pa[kt][1], b2, b3);
                }
        }

        if (pf) CP_WAIT0();
        __syncthreads();
    }

    // quad-reduce partial row sums
#pragma unroll
    for (int m = 0; m < 2; m++)
#pragma unroll
        for (int j = 0; j < 2; j++) {
            rs[m][j] += __shfl_xor_sync(0xffffffffu, rs[m][j], 1);
            rs[m][j] += __shfl_xor_sync(0xffffffffu, rs[m][j], 2);
        }

    // merge key-half partials (wk=1 -> smem, wk=0 adds), per m round
    float* osm = (float*)smem;                 // 64 x 68 floats (reuse Q area)
    float* lsm = (float*)(smem + KS_OFF);      // 64 floats (reuse K area)
    const int rl = wq * 16 + (lane >> 2);
    const int cb = (lane & 3) * 2;
#pragma unroll
    for (int m = 0; m < 2; m++) {
        __syncthreads();
        if (wk == 1) {
#pragma unroll
            for (int nf = 0; nf < 8; nf++) {
                int c = nf * 8 + cb;
                osm[rl * 68 + c]           = O[m][nf][0];
                osm[rl * 68 + c + 1]       = O[m][nf][1];
                osm[(rl + 8) * 68 + c]     = O[m][nf][2];
                osm[(rl + 8) * 68 + c + 1] = O[m][nf][3];
            }
            if ((lane & 3) == 0) {
                lsm[rl] = rs[m][0];
                lsm[rl + 8] = rs[m][1];
            }
        }
        __syncthreads();
        if (wk == 0) {
#pragma unroll
            for (int nf = 0; nf < 8; nf++) {
                int c = nf * 8 + cb;
                O[m][nf][0] += osm[rl * 68 + c];
                O[m][nf][1] += osm[rl * 68 + c + 1];
                O[m][nf][2] += osm[(rl + 8) * 68 + c];
                O[m][nf][3] += osm[(rl + 8) * 68 + c + 1];
            }
            rs[m][0] += lsm[rl];
            rs[m][1] += lsm[rl + 8];
        }
    }

    if (wk == 0) {
#pragma unroll
        for (int m = 0; m < 2; m++) {
            float ia = 1.f / rs[m][0], ib = 1.f / rs[m][1];
            int ra = n0 + wq * 32 + m * 16 + (lane >> 2);
            int rb = ra + 8;
#pragma unroll
            for (int nf = 0; nf < 8; nf++) {
                int c = nf * 8 + cb;
                float2 va; va.x = O[m][nf][0] * ia; va.y = O[m][nf][1] * ia;
                float2 vv; vv.x = O[m][nf][2] * ib; vv.y = O[m][nf][3] * ib;
                *(float2*)&zb[(size_t)ra * 64 + c] = va;
                *(float2*)&zb[(size_t)rb * 64 + c] = vv;
            }
        }
    }
}

// ---------------- q/k/v projections (one proj per block) + fused wprep ------
struct QKVp {
    const float* src[2];
    const float* w[6];
    const float* b[6];
    __nv_bfloat16* dst[6];
    const float* cw;
};
#define QKV_SMEM ((4096 + 64 * 68) * 4)
__global__ __launch_bounds__(256) void qkv_kernel(QKVp P)
{
    extern __shared__ float sm[];
    const int z = blockIdx.z;
    if (z == 6) {
        int o = blockIdx.x * 4 + blockIdx.y;
        for (int kp = threadIdx.x; kp < KDIM; kp += 256) {
            int tap = kp >> 7, ic = kp & 127;
            float v = P.cw[(size_t)o * KDIM + ic * 9 + tap];
            __nv_bfloat16 h = __float2bfloat16(v);
            __nv_bfloat16 l = __float2bfloat16(v - __bfloat162float(h));
            g_Whi[(size_t)o * KDIM + kp] = h;
            g_Wlo[(size_t)o * KDIM + kp] = l;
        }
        return;
    }
    float* ws  = sm;
    float* ins = sm + 4096;
    const float* in = P.src[z / 3];
    const float* w  = P.w[z];
    const float* bi = P.b[z];
    const int b = blockIdx.y, p0 = blockIdx.x * 64, tid = threadIdx.x;
    const float* inB = in + (size_t)b * 64 * HW;
    __nv_bfloat16* outB = P.dst[z] + (size_t)b * HW * 64;

    for (int idx = tid; idx < 4096; idx += 256) {
        int i = idx >> 6, o = idx & 63;
        ws[idx] = w[o * 64 + i];
    }
    for (int idx = tid; idx < 4096; idx += 256) {
        int i = idx >> 6, pp = idx & 63;
        ins[i * 68 + pp] = inB[i * HW + p0 + pp];
    }
    __syncthreads();
    const int tx = tid & 15, ty = tid >> 4;
    const int o0 = ty * 4;
    float acc[4][4];
#pragma unroll
    for (int a = 0; a < 4; a++)
#pragma unroll
        for (int c = 0; c < 4; c++) acc[a][c] = 0.f;
#pragma unroll 4
    for (int i = 0; i < 64; i++) {
        float4 w4 = *(const float4*)&ws[i * 64 + o0];
        float4 v4 = *(const float4*)&ins[i * 68 + tx * 4];
        float wr[4] = {w4.x, w4.y, w4.z, w4.w};
        float iv[4] = {v4.x, v4.y, v4.z, v4.w};
#pragma unroll
        for (int a = 0; a < 4; a++)
#pragma unroll
            for (int c = 0; c < 4; c++) acc[a][c] += wr[a] * iv[c];
    }
    float b0 = bi[o0], b1 = bi[o0 + 1], b2 = bi[o0 + 2], b3 = bi[o0 + 3];
#pragma unroll
    for (int c = 0; c < 4; c++) {
        int p = p0 + tx * 4 + c;
        uint2 u;
        u.x = b2u(__floats2bfloat162_rn(acc[0][c] + b0, acc[1][c] + b1));
        u.y = b2u(__floats2bfloat162_rn(acc[2][c] + b2, acc[3][c] + b3));
        *(uint2*)&outB[(size_t)p * 64 + o0] = u;
    }
}

// ---------------- f-projection (z*x fused), 64-pos tiles -------------------
struct FPp {
    const float* src[2];
    const float* w[2];
    const float* b[2];
    const float* z[2];
    float* comb[2];
};
#define FP_SMEM ((4096 + 64 * 68) * 4)
__global__ __launch_bounds__(256) void fproj_kernel(FPp P)
{
    extern __shared__ float sm[];
    float* ws  = sm;
    float* ins = sm + 4096;
    const int a2 = blockIdx.z;
    const float* in = P.src[a2];
    const float* w  = P.w[a2];
    const float* bi = P.b[a2];
    const int b = blockIdx.y, p0 = blockIdx.x * 64, tid = threadIdx.x;
    const float* inB = in + (size_t)b * 64 * HW;
    const float* zB  = P.z[a2] + (size_t)b * HW * 64;
    float* out = P.comb[a2];

    for (int idx = tid; idx < 4096; idx += 256) {
        int i = idx >> 6, o = idx & 63;
        ws[idx] = w[o * 64 + i];
    }
    for (int idx = tid; idx < 4096; idx += 256) {
        int i = idx >> 6, pp = idx & 63;
        int p = p0 + pp;
        ins[i * 68 + pp] = zB[(size_t)i * HW + p] * inB[i * HW + p];
    }
    __syncthreads();
    const int tx = tid & 15, ty = tid >> 4;
    float acc[4][4];
#pragma unroll
    for (int a = 0; a < 4; a++)
#pragma unroll
        for (int c = 0; c < 4; c++) acc[a][c] = 0.f;
#pragma unroll 4
    for (int i = 0; i < 64; i++) {
        float4 w4 = *(const float4*)&ws[i * 64 + ty * 4];
        float4 v4 = *(const float4*)&ins[i * 68 + tx * 4];
        float wr[4] = {w4.x, w4.y, w4.z, w4.w};
        float iv[4] = {v4.x, v4.y, v4.z, v4.w};
#pragma unroll
        for (int a = 0; a < 4; a++)
#pragma unroll
            for (int c = 0; c < 4; c++) acc[a][c] += wr[a] * iv[c];
    }
#pragma unroll
    for (int a = 0; a < 4; a++) {
        int o = ty * 4 + a;
        float bb = bi[o];
        int p = p0 + tx * 4;
        float4 r  = *(const float4*)&inB[o * HW + p];
        r.x += acc[a][0] + bb; r.y += acc[a][1] + bb;
        r.z += acc[a][2] + bb; r.w += acc[a][3] + bb;
        *(float4*)&out[(size_t)b * 128 * HW + o * HW + p] = r;
    }
}

// ---------------- conv as GEMM: tap-major K, uniform-shift im2col -----------
#define AST 272
#define BST 80
#define A_BYTES (32 * AST)
#define B_BYTES (128 * BST)
#define STAGE_BYTES (2 * A_BYTES + 2 * B_BYTES)
#define CG_SMEM (2 * STAGE_BYTES)

__device__ __forceinline__ void im2col_tap(int ic, int dy, int dx, int b,
                                           int pin, int seg,
                                           uint4& hi, uint4& lo) {
    int p = pin + seg * 8;
    int r = p >> 6, x = p & 63;
    int rr = r + dy - 1;
    bool rowok = ((unsigned)rr < 64u);
    const float* row = &g_comb[b][ic][rr * 64];
    float4 f0, f1;
    if (rowok) {
        f0 = *(const float4*)(row + x);
        f1 = *(const float4*)(row + x + 4);
    } else {
        f0 = make_float4(0.f, 0.f, 0.f, 0.f);
        f1 = f0;
    }
    float v[8];
    if (dx == 1) {
        v[0] = f0.x; v[1] = f0.y; v[2] = f0.z; v[3] = f0.w;
        v[4] = f1.x; v[5] = f1.y; v[6] = f1.z; v[7] = f1.w;
    } else if (dx == 0) {
        float L = (rowok && x > 0) ? row[x - 1] : 0.f;
        v[0] = L;    v[1] = f0.x; v[2] = f0.y; v[3] = f0.z;
        v[4] = f0.w; v[5] = f1.x; v[6] = f1.y; v[7] = f1.z;
    } else {
        float R = (rowok && x < 56) ? row[x + 8] : 0.f;
        v[0] = f0.y; v[1] = f0.z; v[2] = f0.w; v[3] = f1.x;
        v[4] = f1.y; v[5] = f1.z; v[6] = f1.w; v[7] = R;
    }
    uint32_t* hp = (uint32_t*)&hi;
    uint32_t* lp = (uint32_t*)&lo;
#pragma unroll
    for (int e2 = 0; e2 < 4; e2++) {
        __nv_bfloat16 h0 = __float2bfloat16(v[2 * e2]);
        __nv_bfloat16 h1 = __float2bfloat16(v[2 * e2 + 1]);
        __nv_bfloat162 hh; hh.x = h0; hh.y = h1;
        __nv_bfloat162 ll;
        ll.x = __float2bfloat16(v[2 * e2] - __bfloat162float(h0));
        ll.y = __float2bfloat16(v[2 * e2 + 1] - __bfloat162float(h1));
        hp[e2] = b2u(hh);
        lp[e2] = b2u(ll);
    }
}

__global__ __launch_bounds__(256, 2) void convgemm_kernel(
    const float* __restrict__ cb)
{
    extern __shared__ char csm[];
    const uint32_t smb = smem_u32(csm);
    const int tid = threadIdx.x, w = tid >> 5, lane = tid & 31;
    const int wp = w & 1, wo = w >> 1;
    const int p0 = blockIdx.x * 128;
    const int o0 = blockIdx.y * 128;
    const int bb_ = blockIdx.x >> 5, pin = p0 & 4095;
    const int pblk = blockIdx.x & 31;

    const int k_it0 = tid >> 4,         seg_it0 = tid & 15;
    const int k_it1 = (256 + tid) >> 4, seg_it1 = tid & 15;

    {
        uint4 hi, lo;
        im2col_tap(k_it0, 0, 0, bb_, pin, seg_it0, hi, lo);
        *(uint4*)(csm + k_it0 * AST + seg_it0 * 16) = hi;
        *(uint4*)(csm + A_BYTES + k_it0 * AST + seg_it0 * 16) = lo;
        im2col_tap(k_it1, 0, 0, bb_, pin, seg_it1, hi, lo);
        *(uint4*)(csm + k_it1 * AST + seg_it1 * 16) = hi;
        *(uint4*)(csm + A_BYTES + k_it1 * AST + seg_it1 * 16) = lo;
        for (int it = 0; it < 4; it++) {
            int flat = it * 256 + tid;
            int v = flat >> 9, rem = flat & 511;
            int o = rem >> 2, seg = rem & 3;
            const __nv_bfloat16* s = (v ? g_Wlo : g_Whi) + (size_t)(o0 + o) * KDIM + seg * 8;
            *(uint4*)(csm + 2 * A_BYTES + v * B_BYTES + o * BST + seg * 16) = *(const uint4*)s;
        }
    }
    __syncthreads();

    float acc[4][4][4];
#pragma unroll
    for (int i = 0; i < 4; i++)
#pragma unroll
        for (int j = 0; j < 4; j++)
#pragma unroll
            for (int e = 0; e < 4; e++) acc[i][j][e] = 0.f;

    const uint32_t arow  = (uint32_t)(((lane >> 4) & 1) * 8 + (lane & 7));
    const uint32_t apcol = (uint32_t)(((lane >> 3) & 1) * 8);
    const uint32_t brow  = (uint32_t)(((lane >> 4) << 3) + (lane & 7));
    const uint32_t bkcs  = (uint32_t)(((lane >> 3) & 1) * 8);

    for (int t = 0; t < 36; t++) {
        const int cur = t & 1;
        const uint32_t Abase = smb + cur * STAGE_BYTES;
        const uint32_t Bbase = Abase + 2 * A_BYTES;
        const bool pf = (t + 1 < 36);

        if (pf) {
            int k0 = (t + 1) * 32;
            uint32_t Bn = smb + (cur ^ 1) * STAGE_BYTES + 2 * A_BYTES;
#pragma unroll
            for (int it = 0; it < 4; it++) {
                int flat = it * 256 + tid;
                int v = flat >> 9, rem = flat & 511;
                int o = rem >> 2, seg = rem & 3;
                cp_async16(Bn + v * B_BYTES + o * BST + seg * 16,
                           (v ? g_Wlo : g_Whi) + (size_t)(o0 + o) * KDIM + k0 + seg * 8);
            }
            CP_COMMIT();
        }

        uint4 pfAh0, pfAl0, pfAh1, pfAl1;
        if (pf) {
            int tn = t + 1;
            int tap = tn >> 2;
            int ic0 = (tn & 3) * 32;
            int dy = tap / 3, dx = tap - dy * 3;
            im2col_tap(ic0 + k_it0, dy, dx, bb_, pin, seg_it0, pfAh0, pfAl0);
            im2col_tap(ic0 + k_it1, dy, dx, bb_, pin, seg_it1, pfAh1, pfAl1);
        }

#pragma unroll
        for (int kf = 0; kf < 2; kf++) {
            uint32_t bh[2][4], bl[2][4];
#pragma unroll
            for (int og = 0; og < 2; og++) {
                uint32_t baddr = Bbase + (wo * 32 + og * 16 + brow) * BST
                               + (kf * 16 + bkcs) * 2;
                ldsm_x4(bh[og][0], bh[og][1], bh[og][2], bh[og][3], baddr);
                ldsm_x4(bl[og][0], bl[og][1], bl[og][2], bl[og][3], baddr + B_BYTES);
            }
#pragma unroll
            for (int mf = 0; mf < 4; mf++) {
                uint32_t aaddr = Abase + (kf * 16 + arow) * AST
                               + (wp * 64 + mf * 16 + apcol) * 2;
                uint32_t ah[4], al[4];
                ldsm_x4_t(ah[0], ah[1], ah[2], ah[3], aaddr);
                ldsm_x4_t(al[0], al[1], al[2], al[3], aaddr + A_BYTES);
#pragma unroll
                for (int og = 0; og < 2; og++) {
                    mma16816(acc[mf][og * 2],     ah, bh[og][0], bh[og][1]);
                    mma16816(acc[mf][og * 2 + 1], ah, bh[og][2], bh[og][3]);
                    mma16816(acc[mf][og * 2],     ah, bl[og][0], bl[og][1]);
                    mma16816(acc[mf][og * 2 + 1], ah, bl[og][2], bl[og][3]);
                    mma16816(acc[mf][og * 2],     al, bh[og][0], bh[og][1]);
                    mma16816(acc[mf][og * 2 + 1], al, bh[og][2], bh[og][3]);
                }
            }
        }

        if (pf) {
            char* stn = csm + (cur ^ 1) * STAGE_BYTES;
            *(uint4*)(stn + k_it0 * AST + seg_it0 * 16) = pfAh0;
            *(uint4*)(stn + A_BYTES + k_it0 * AST + seg_it0 * 16) = pfAl0;
            *(uint4*)(stn + k_it1 * AST + seg_it1 * 16) = pfAh1;
            *(uint4*)(stn + A_BYTES + k_it1 * AST + seg_it1 * 16) = pfAl1;
            CP_WAIT0();
        }
        __syncthreads();
    }

    float* osm = (float*)csm;
    const int prow = wp * 64 + (lane >> 2);
    const int ocol = (lane & 3) * 2;
#pragma unroll
    for (int mf = 0; mf < 4; mf++) {
#pragma unroll
        for (int nf = 0; nf < 4; nf++) {
            int oc = wo * 32 + nf * 8 + ocol;
            int pr = prow + mf * 16;
            osm[oc * 132 + pr]           = acc[mf][nf][0];
            osm[(oc + 1) * 132 + pr]     = acc[mf][nf][1];
            osm[oc * 132 + pr + 8]       = acc[mf][nf][2];
            osm[(oc + 1) * 132 + pr + 8] = acc[mf][nf][3];
        }
    }
    __syncthreads();
#pragma unroll
    for (int it = 0; it < 16; it++) {
        int i = it * 256 + tid;
        int o = i >> 5, seg = i & 31;
        float4 v = *(float4*)&osm[o * 132 + seg * 4];
        float bb = cb[o0 + o];
        v.x += bb; v.y += bb; v.z += bb; v.w += bb;
        *(float4*)&g_y[bb_][o0 + o][pin + seg * 4] = v;
        float s = v.x + v.y + v.z + v.w;
        float q = v.x * v.x + v.y * v.y + v.z * v.z + v.w * v.w;
#pragma unroll
        for (int d = 16; d > 0; d >>= 1) {
            s += __shfl_xor_sync(0xffffffffu, s, d);
            q += __shfl_xor_sync(0xffffffffu, q, d);
        }
        if (lane == 0) {
            g_psum[bb_][pblk][o0 + o]  = s;
            g_psumq[bb_][pblk][o0 + o] = q;
        }
    }
}

// ---------------- GroupNorm finalize ----------------------------------------
__global__ __launch_bounds__(256) void gnfin_kernel()
{
    int idx = blockIdx.x * 256 + threadIdx.x;
    int b = idx >> 8, o = idx & 255;
    float s = 0.f, q = 0.f;
#pragma unroll
    for (int pb = 0; pb < 32; pb++) {
        s += g_psum[b][pb][o];
        q += g_psumq[b][pb][o];
    }
    float mean = s * (1.f / HW);
    float var  = q * (1.f / HW) - mean * mean;
    g_mean[b][o] = mean;
    g_rstd[b][o] = rsqrtf(var + 1e-5f);
}

// ---------------- LSTM gates (float4 vectorized) ----------------------------
__global__ __launch_bounds__(256) void gates_kernel(
    const float* __restrict__ cprev, const float* __restrict__ gnw,
    const float* __restrict__ gnb, float* __restrict__ out)
{
    int idx4 = blockIdx.x * 256 + threadIdx.x;
    int base = idx4 * 4;
    int p  = base & (HW - 1);
    int ch = (base >> 12) & 63;
    int b  = base >> 18;

    float4 yi = *(const float4*)&g_y[b][ch][p];
    float4 yf = *(const float4*)&g_y[b][ch + 64][p];
    float4 yo = *(const float4*)&g_y[b][ch + 128][p];
    float4 yg = *(const float4*)&g_y[b][ch + 192][p];
    float4 cp4 = *(const float4*)&cprev[base];

    float mi = g_mean[b][ch],      ri = g_rstd[b][ch];
    float mf = g_mean[b][ch + 64], rf = g_rstd[b][ch + 64];
    float mo = g_mean[b][ch + 128], ro = g_rstd[b][ch + 128];
    float mg = g_mean[b][ch + 192], rg = g_rstd[b][ch + 192];
    float wi = gnw[ch],       bi_ = gnb[ch];
    float wf = gnw[ch + 64],  bf_ = gnb[ch + 64];
    float wo_ = gnw[ch + 128], bo_ = gnb[ch + 128];
    float wg = gnw[ch + 192], bg_ = gnb[ch + 192];

    float yiv[4] = {yi.x, yi.y, yi.z, yi.w};
    float yfv[4] = {yf.x, yf.y, yf.z, yf.w};
    float yov[4] = {yo.x, yo.y, yo.z, yo.w};
    float ygv[4] = {yg.x, yg.y, yg.z, yg.w};
    float cpv[4] = {cp4.x, cp4.y, cp4.z, cp4.w};
    float hnv[4], cnv[4];
#pragma unroll
    for (int e = 0; e < 4; e++) {
        float ni = (yiv[e] - mi) * ri * wi + bi_;
        float nf = (yfv[e] - mf) * rf * wf + bf_;
        float no_ = (yov[e] - mo) * ro * wo_ + bo_;
        float ng = (ygv[e] - mg) * rg * wg + bg_;
        float ig = 1.f / (1.f + __expf(-ni));
        float fg = 1.f / (1.f + __expf(-nf));
        float og = 1.f / (1.f + __expf(-no_));
        float gg = tanhf(ng);
        float cn = fg * cpv[e] + ig * gg;
        hnv[e] = og * tanhf(cn);
        cnv[e] = cn;
    }
    float4 hn4, cn4;
    hn4.x = hnv[0]; hn4.y = hnv[1]; hn4.z = hnv[2]; hn4.w = hnv[3];
    cn4.x = cnv[0]; cn4.y = cnv[1]; cn4.z = cnv[2]; cn4.w = cnv[3];
    *(float4*)&out[base] = hn4;
    *(float4*)&out[base + BATCH * 64 * HW] = cn4;
}

// ---------------- launch -----------------------------------------------------
extern "C" void kernel_launch(void* const* d_in, const int* in_sizes, int n_in,
                              void* d_out, int out_size)
{
    (void)in_sizes; (void)n_in; (void)out_size;
    const float* x = (const float*)d_in[0];
    const float* h = (const float*)d_in[1];
    const float* c = (const float*)d_in[2];
    const float* aw[2][8];
    for (int a = 0; a < 2; a++)
        for (int j = 0; j < 8; j++)
            aw[a][j] = (const float*)d_in[3 + a * 8 + j];
    const float* conv_w = (const float*)d_in[19];
    const float* conv_b = (const float*)d_in[20];
    const float* gn_w   = (const float*)d_in[21];
    const float* gn_b   = (const float*)d_in[22];
    float* out = (float*)d_out;

    __nv_bfloat16 *bq, *bk, *bv;
    float *z, *comb;
    cudaGetSymbolAddress((void**)&bq, g_bq);
    cudaGetSymbolAddress((void**)&bk, g_bk);
    cudaGetSymbolAddress((void**)&bv, g_bv);
    cudaGetSymbolAddress((void**)&z, g_z);
    cudaGetSymbolAddress((void**)&comb, g_comb);

    cudaFuncSetAttribute(qkv_kernel,
                         cudaFuncAttributeMaxDynamicSharedMemorySize, QKV_SMEM);
    cudaFuncSetAttribute(fproj_kernel,
                         cudaFuncAttributeMaxDynamicSharedMemorySize, FP_SMEM);
    cudaFuncSetAttribute(flash_mma_kernel,
                         cudaFuncAttributeMaxDynamicSharedMemorySize, FL_SMEM);
    cudaFuncSetAttribute(convgemm_kernel,
                         cudaFuncAttributeMaxDynamicSharedMemorySize, CG_SMEM);

    const size_t half = (size_t)BATCH * HW * 64;

    // launch 0: qkv projections + fused conv-weight prep (z == 6)
    QKVp qp;
    qp.src[0] = x; qp.src[1] = h;
    for (int a = 0; a < 2; a++)
        for (int t = 0; t < 3; t++) {
            qp.w[a * 3 + t] = aw[a][2 * t];
            qp.b[a * 3 + t] = aw[a][2 * t + 1];
        }
    qp.dst[0] = bq;        qp.dst[1] = bk;        qp.dst[2] = bv;
    qp.dst[3] = bq + half; qp.dst[4] = bk + half; qp.dst[5] = bv + half;
    qp.cw = conv_w;
    qkv_kernel<<<dim3(64, BATCH, 7), 256, QKV_SMEM>>>(qp);

    // launch 1: flash attention (BM=128, 4q x 2k warps, 2 CTAs/SM)
    flash_mma_kernel<<<dim3(32, BATCH, 2), 256, FL_SMEM>>>(bq, bk, bv, z);

    // launch 2
    FPp fp;
    fp.src[0] = x; fp.src[1] = h;
    for (int a = 0; a < 2; a++) { fp.w[a] = aw[a][6]; fp.b[a] = aw[a][7]; }
    fp.z[0] = z; fp.z[1] = z + half;
    fp.comb[0] = comb; fp.comb[1] = comb + (size_t)64 * HW;
    fproj_kernel<<<dim3(64, BATCH, 2), 256, FP_SMEM>>>(fp);

    // launch 3 (ncu-profiled slot)
    convgemm_kernel<<<dim3(NPOS / 128, 2), 256, CG_SMEM>>>(conv_b);

    gnfin_kernel<<<4, 256>>>();
    gates_kernel<<<(BATCH * 64 * HW) / 1024, 256>>>(c, gn_w, gn_b, out);
}

// round 16
// speedup vs baseline: 1.1505x; 1.1505x over previous
#include <cuda_runtime.h>
#include <cuda_bf16.h>
#include <cstdint>

#define HW 4096
#define BATCH 4
#define KDIM 1152
#define NPOS 16384

// ---------------- scratch (device globals) ---------------------------------
__device__ __nv_bfloat16 g_bq[2 * BATCH * HW * 64];
__device__ __nv_bfloat16 g_bk[2 * BATCH * HW * 64];
__device__ __nv_bfloat16 g_bv[2 * BATCH * HW * 64];
__device__ float g_z[2][BATCH][HW * 64];
__device__ float g_comb[BATCH][128][HW];
__device__ float g_y[BATCH][256][HW];
__device__ float g_mean[BATCH][256];
__device__ float g_rstd[BATCH][256];
__device__ float g_psum[BATCH][32][256];
__device__ float g_psumq[BATCH][32][256];
// W' permuted: k' = (ky*3+kx)*128 + ic
__device__ __nv_bfloat16 g_Whi[256 * KDIM];
__device__ __nv_bfloat16 g_Wlo[256 * KDIM];

// ---------------- helpers ---------------------------------------------------
__device__ __forceinline__ uint32_t smem_u32(const void* p) {
    uint32_t a;
    asm("{ .reg .u64 t; cvta.to.shared.u64 t, %1; cvt.u32.u64 %0, t; }"
        : "=r"(a) : "l"(p));
    return a;
}
__device__ __forceinline__ void ldsm_x4(uint32_t& r0, uint32_t& r1,
                                        uint32_t& r2, uint32_t& r3, uint32_t a) {
    asm volatile("ldmatrix.sync.aligned.m8n8.x4.shared.b16 {%0,%1,%2,%3}, [%4];"
                 : "=r"(r0), "=r"(r1), "=r"(r2), "=r"(r3) : "r"(a));
}
__device__ __forceinline__ void ldsm_x4_t(uint32_t& r0, uint32_t& r1,
                                          uint32_t& r2, uint32_t& r3, uint32_t a) {
    asm volatile("ldmatrix.sync.aligned.m8n8.x4.trans.shared.b16 {%0,%1,%2,%3}, [%4];"
                 : "=r"(r0), "=r"(r1), "=r"(r2), "=r"(r3) : "r"(a));
}
__device__ __forceinline__ void mma16816(float d[4], const uint32_t a[4],
                                         uint32_t b0, uint32_t b1) {
    asm volatile(
        "mma.sync.aligned.m16n8k16.row.col.f32.bf16.bf16.f32 "
        "{%0,%1,%2,%3},{%4,%5,%6,%7},{%8,%9},{%0,%1,%2,%3};"
        : "+f"(d[0]), "+f"(d[1]), "+f"(d[2]), "+f"(d[3])
        : "r"(a[0]), "r"(a[1]), "r"(a[2]), "r"(a[3]), "r"(b0), "r"(b1));
}
__device__ __forceinline__ uint32_t b2u(__nv_bfloat162 v) {
    return *reinterpret_cast<uint32_t*>(&v);
}
__device__ __forceinline__ void cp_async16(uint32_t dst, const void* src) {
    asm volatile("cp.async.ca.shared.global [%0], [%1], 16;" :: "r"(dst), "l"(src));
}
#define CP_COMMIT() asm volatile("cp.async.commit_group;" ::: "memory")
#define CP_WAIT0()  asm volatile("cp.async.wait_group 0;" ::: "memory")

// ---------------- flash attention: 512 thr, BM=256, 8q x 2k warps ----------
#define QSTR 144
#define QS_OFF 0
#define KS_OFF 36864
#define VS_OFF 55296
#define FL_SMEM 73728

__global__ __launch_bounds__(512, 1) void flash_mma_kernel(
    const __nv_bfloat16* __restrict__ bq, const __nv_bfloat16* __restrict__ bk,
    const __nv_bfloat16* __restrict__ bv, float* __restrict__ gz)
{
    extern __shared__ char smem[];
    const uint32_t smb = smem_u32(smem);
    const int tid = threadIdx.x, w = tid >> 5, lane = tid & 31;
    const int wq = w >> 1, wk = w & 1;
    const int ab = blockIdx.z * BATCH + blockIdx.y;
    const int n0 = blockIdx.x * 256;
    const __nv_bfloat16* qb = bq + (size_t)ab * HW * 64;
    const __nv_bfloat16* kb = bk + (size_t)ab * HW * 64;
    const __nv_bfloat16* vb = bv + (size_t)ab * HW * 64;
    float* zb = gz + (size_t)ab * HW * 64;

    // Q tile: 256 rows x 64 d
    {
        int r = tid >> 1, sg = (tid & 1) * 32;
        const uint4* s = (const uint4*)(qb + (size_t)(n0 + r) * 64 + sg);
        uint4* d = (uint4*)(smem + QS_OFF + r * QSTR + sg * 2);
        d[0] = s[0]; d[1] = s[1]; d[2] = s[2]; d[3] = s[3];
    }
    // K/V tile 0 (64 keys)
    const int kr = tid >> 3, ksg = (tid & 7) * 8;
    {
        *(uint4*)(smem + KS_OFF + kr * QSTR + ksg * 2) =
            *(const uint4*)(kb + (size_t)kr * 64 + ksg);
        *(uint4*)(smem + VS_OFF + kr * QSTR + ksg * 2) =
            *(const uint4*)(vb + (size_t)kr * 64 + ksg);
    }
    __syncthreads();

    float O[2][8][4];
#pragma unroll
    for (int m = 0; m < 2; m++)
#pragma unroll
        for (int n = 0; n < 8; n++)
#pragma unroll
            for (int e = 0; e < 4; e++) O[m][n][e] = 0.f;
    float rs[2][2] = {{0.f, 0.f}, {0.f, 0.f}};

    const uint32_t aq   = (uint32_t)(((lane >> 3) & 1) * 8 + (lane & 7));
    const uint32_t acol = (uint32_t)((lane >> 4) * 8);
    const uint32_t krow = (uint32_t)(((lane >> 4) << 3) + (lane & 7));
    const uint32_t kcs  = (uint32_t)(((lane >> 3) & 1) * 8);
    const uint32_t vrow = (uint32_t)(((lane >> 3) & 1) * 8 + (lane & 7));
    const uint32_t vcs  = (uint32_t)((lane >> 4) * 8);

    for (int t = 0; t < 64; t++) {
        const int cur = t & 1;
        const uint32_t Kst = smb + KS_OFF + cur * 9216;
        const uint32_t Vst = smb + VS_OFF + cur * 9216;
        const bool pf = (t + 1 < 64);

        if (pf) {
            size_t off = ((size_t)((t + 1) * 64 + kr)) * 64 + ksg;
            cp_async16(smb + KS_OFF + (cur ^ 1) * 9216 + kr * QSTR + ksg * 2,
                       kb + off);
            cp_async16(smb + VS_OFF + (cur ^ 1) * 9216 + kr * QSTR + ksg * 2,
                       vb + off);
            CP_COMMIT();
        }

        // ---- S[32 q x 32 k(this half)] ----
        float S[2][4][4];
#pragma unroll
        for (int m = 0; m < 2; m++)
#pragma unroll
            for (int n = 0; n < 4; n++)
#pragma unroll
                for (int e = 0; e < 4; e++) S[m][n][e] = 0.f;
#pragma unroll
        for (int ks = 0; ks < 4; ks++) {
            uint32_t qa0[4], qa1[4];
            ldsm_x4(qa0[0], qa0[1], qa0[2], qa0[3],
                    smb + QS_OFF + (wq * 32 + aq) * QSTR + (ks * 16 + acol) * 2);
            ldsm_x4(qa1[0], qa1[1], qa1[2], qa1[3],
                    smb + QS_OFF + (wq * 32 + 16 + aq) * QSTR + (ks * 16 + acol) * 2);
#pragma unroll
            for (int np = 0; np < 2; np++) {
                uint32_t b0, b1, b2, b3;
                ldsm_x4(b0, b1, b2, b3,
                        Kst + (wk * 32 + np * 16 + krow) * QSTR + (ks * 16 + kcs) * 2);
                mma16816(S[0][np * 2],     qa0, b0, b1);
                mma16816(S[0][np * 2 + 1], qa0, b2, b3);
                mma16816(S[1][np * 2],     qa1, b0, b1);
                mma16816(S[1][np * 2 + 1], qa1, b2, b3);
            }
        }

        // ---- exp + partial row sums ----
#pragma unroll
        for (int m = 0; m < 2; m++)
#pragma unroll
            for (int n = 0; n < 4; n++) {
                S[m][n][0] = __expf(S[m][n][0]); S[m][n][1] = __expf(S[m][n][1]);
                S[m][n][2] = __expf(S[m][n][2]); S[m][n][3] = __expf(S[m][n][3]);
                rs[m][0] += S[m][n][0] + S[m][n][1];
                rs[m][1] += S[m][n][2] + S[m][n][3];
            }
        uint32_t pa[2][2][4];
#pragma unroll
        for (int kt = 0; kt < 2; kt++)
#pragma unroll
            for (int m = 0; m < 2; m++) {
                pa[kt][m][0] = b2u(__floats2bfloat162_rn(S[m][2*kt][0],   S[m][2*kt][1]));
                pa[kt][m][1] = b2u(__floats2bfloat162_rn(S[m][2*kt][2],   S[m][2*kt][3]));
                pa[kt][m][2] = b2u(__floats2bfloat162_rn(S[m][2*kt+1][0], S[m][2*kt+1][1]));
                pa[kt][m][3] = b2u(__floats2bfloat162_rn(S[m][2*kt+1][2], S[m][2*kt+1][3]));
            }

        // ---- O += P.V over this key half ----
#pragma unroll
        for (int kt = 0; kt < 2; kt++)
#pragma unroll
            for (int np = 0; np < 4; np++) {
                uint32_t b0, b1, b2, b3;
                ldsm_x4_t(b0, b1, b2, b3,
                          Vst + (wk * 32 + kt * 16 + vrow) * QSTR + (np * 16 + vcs) * 2);
                mma16816(O[0][np * 2],     pa[kt][0], b0, b1);
                mma16816(O[0][np * 2 + 1], pa[kt][0], b2, b3);
                mma16816(O[1][np * 2],     pa[kt][1], b0, b1);
                mma16816(O[1][np * 2 + 1], pa[kt][1], b2, b3);
            }

        if (pf) CP_WAIT0();
        __syncthreads();
    }

    // quad-reduce partial row sums
#pragma unroll
    for (int m = 0; m < 2; m++)
#pragma unroll
        for (int j = 0; j < 2; j++) {
            rs[m][j] += __shfl_xor_sync(0xffffffffu, rs[m][j], 1);
            rs[m][j] += __shfl_xor_sync(0xffffffffu, rs[m][j], 2);
        }

    // merge key-half partials (wk=1 -> smem, wk=0 adds), per m round
    float* osm = (float*)smem;                 // reuse Q area
    float* lsm = (float*)(smem + KS_OFF);      // reuse K area
    const int rl = wq * 16 + (lane >> 2);
    const int cb = (lane & 3) * 2;
#pragma unroll
    for (int m = 0; m < 2; m++) {
        __syncthreads();
        if (wk == 1) {
#pragma unroll
            for (int nf = 0; nf < 8; nf++) {
                int c = nf * 8 + cb;
                osm[rl * 68 + c]           = O[m][nf][0];
                osm[rl * 68 + c + 1]       = O[m][nf][1];
                osm[(rl + 8) * 68 + c]     = O[m][nf][2];
                osm[(rl + 8) * 68 + c + 1] = O[m][nf][3];
            }
            if ((lane & 3) == 0) {
                lsm[rl] = rs[m][0];
                lsm[rl + 8] = rs[m][1];
            }
        }
        __syncthreads();
        if (wk == 0) {
#pragma unroll
            for (int nf = 0; nf < 8; nf++) {
                int c = nf * 8 + cb;
                O[m][nf][0] += osm[rl * 68 + c];
                O[m][nf][1] += osm[rl * 68 + c + 1];
                O[m][nf][2] += osm[(rl + 8) * 68 + c];
                O[m][nf][3] += osm[(rl + 8) * 68 + c + 1];
            }
            rs[m][0] += lsm[rl];
            rs[m][1] += lsm[rl + 8];
        }
    }

    if (wk == 0) {
#pragma unroll
        for (int m = 0; m < 2; m++) {
            float ia = 1.f / rs[m][0], ib = 1.f / rs[m][1];
            int ra = n0 + wq * 32 + m * 16 + (lane >> 2);
            int rb = ra + 8;
#pragma unroll
            for (int nf = 0; nf < 8; nf++) {
                int c = nf * 8 + cb;
                float2 va; va.x = O[m][nf][0] * ia; va.y = O[m][nf][1] * ia;
                float2 vv; vv.x = O[m][nf][2] * ib; vv.y = O[m][nf][3] * ib;
                *(float2*)&zb[(size_t)ra * 64 + c] = va;
                *(float2*)&zb[(size_t)rb * 64 + c] = vv;
            }
        }
    }
}

// ---------------- q/k/v projections (one proj per block) + fused wprep ------
struct QKVp {
    const float* src[2];
    const float* w[6];
    const float* b[6];
    __nv_bfloat16* dst[6];
    const float* cw;
};
#define QKV_SMEM ((4096 + 64 * 68) * 4)
__global__ __launch_bounds__(256) void qkv_kernel(QKVp P)
{
    extern __shared__ float sm[];
    const int z = blockIdx.z;
    if (z == 6) {
        int o = blockIdx.x * 4 + blockIdx.y;
        for (int kp = threadIdx.x; kp < KDIM; kp += 256) {
            int tap = kp >> 7, ic = kp & 127;
            float v = P.cw[(size_t)o * KDIM + ic * 9 + tap];
            __nv_bfloat16 h = __float2bfloat16(v);
            __nv_bfloat16 l = __float2bfloat16(v - __bfloat162float(h));
            g_Whi[(size_t)o * KDIM + kp] = h;
            g_Wlo[(size_t)o * KDIM + kp] = l;
        }
        return;
    }
    float* ws  = sm;
    float* ins = sm + 4096;
    const float* in = P.src[z / 3];
    const float* w  = P.w[z];
    const float* bi = P.b[z];
    const int b = blockIdx.y, p0 = blockIdx.x * 64, tid = threadIdx.x;
    const float* inB = in + (size_t)b * 64 * HW;
    __nv_bfloat16* outB = P.dst[z] + (size_t)b * HW * 64;

    for (int idx = tid; idx < 4096; idx += 256) {
        int i = idx >> 6, o = idx & 63;
        ws[idx] = w[o * 64 + i];
    }
    for (int idx = tid; idx < 4096; idx += 256) {
        int i = idx >> 6, pp = idx & 63;
        ins[i * 68 + pp] = inB[i * HW + p0 + pp];
    }
    __syncthreads();
    const int tx = tid & 15, ty = tid >> 4;
    const int o0 = ty * 4;
    float acc[4][4];
#pragma unroll
    for (int a = 0; a < 4; a++)
#pragma unroll
        for (int c = 0; c < 4; c++) acc[a][c] = 0.f;
#pragma unroll 4
    for (int i = 0; i < 64; i++) {
        float4 w4 = *(const float4*)&ws[i * 64 + o0];
        float4 v4 = *(const float4*)&ins[i * 68 + tx * 4];
        float wr[4] = {w4.x, w4.y, w4.z, w4.w};
        float iv[4] = {v4.x, v4.y, v4.z, v4.w};
#pragma unroll
        for (int a = 0; a < 4; a++)
#pragma unroll
            for (int c = 0; c < 4; c++) acc[a][c] += wr[a] * iv[c];
    }
    float b0 = bi[o0], b1 = bi[o0 + 1], b2 = bi[o0 + 2], b3 = bi[o0 + 3];
#pragma unroll
    for (int c = 0; c < 4; c++) {
        int p = p0 + tx * 4 + c;
        uint2 u;
        u.x = b2u(__floats2bfloat162_rn(acc[0][c] + b0, acc[1][c] + b1));
        u.y = b2u(__floats2bfloat162_rn(acc[2][c] + b2, acc[3][c] + b3));
        *(uint2*)&outB[(size_t)p * 64 + o0] = u;
    }
}

// ---------------- f-projection (z*x fused), 64-pos tiles -------------------
struct FPp {
    const float* src[2];
    const float* w[2];
    const float* b[2];
    const float* z[2];
    float* comb[2];
};
#define FP_SMEM ((4096 + 64 * 68) * 4)
__global__ __launch_bounds__(256) void fproj_kernel(FPp P)
{
    extern __shared__ float sm[];
    float* ws  = sm;
    float* ins = sm + 4096;
    const int a2 = blockIdx.z;
    const float* in = P.src[a2];
    const float* w  = P.w[a2];
    const float* bi = P.b[a2];
    const int b = blockIdx.y, p0 = blockIdx.x * 64, tid = threadIdx.x;
    const float* inB = in + (size_t)b * 64 * HW;
    const float* zB  = P.z[a2] + (size_t)b * HW * 64;
    float* out = P.comb[a2];

    for (int idx = tid; idx < 4096; idx += 256) {
        int i = idx >> 6, o = idx & 63;
        ws[idx] = w[o * 64 + i];
    }
    for (int idx = tid; idx < 4096; idx += 256) {
        int i = idx >> 6, pp = idx & 63;
        int p = p0 + pp;
        ins[i * 68 + pp] = zB[(size_t)i * HW + p] * inB[i * HW + p];
    }
    __syncthreads();
    const int tx = tid & 15, ty = tid >> 4;
    float acc[4][4];
#pragma unroll
    for (int a = 0; a < 4; a++)
#pragma unroll
        for (int c = 0; c < 4; c++) acc[a][c] = 0.f;
#pragma unroll 4
    for (int i = 0; i < 64; i++) {
        float4 w4 = *(const float4*)&ws[i * 64 + ty * 4];
        float4 v4 = *(const float4*)&ins[i * 68 + tx * 4];
        float wr[4] = {w4.x, w4.y, w4.z, w4.w};
        float iv[4] = {v4.x, v4.y, v4.z, v4.w};
#pragma unroll
        for (int a = 0; a < 4; a++)
#pragma unroll
            for (int c = 0; c < 4; c++) acc[a][c] += wr[a] * iv[c];
    }
#pragma unroll
    for (int a = 0; a < 4; a++) {
        int o = ty * 4 + a;
        float bb = bi[o];
        int p = p0 + tx * 4;
        float4 r  = *(const float4*)&inB[o * HW + p];
        r.x += acc[a][0] + bb; r.y += acc[a][1] + bb;
        r.z += acc[a][2] + bb; r.w += acc[a][3] + bb;
        *(float4*)&out[(size_t)b * 128 * HW + o * HW + p] = r;
    }
}

// ---------------- conv as GEMM: tap-major K, uniform-shift im2col -----------
#define AST 272
#define BST 80
#define A_BYTES (32 * AST)
#define B_BYTES (128 * BST)
#define STAGE_BYTES (2 * A_BYTES + 2 * B_BYTES)
#define CG_SMEM (2 * STAGE_BYTES)

__device__ __forceinline__ void im2col_tap(int ic, int dy, int dx, int b,
                                           int pin, int seg,
                                           uint4& hi, uint4& lo) {
    int p = pin + seg * 8;
    int r = p >> 6, x = p & 63;
    int rr = r + dy - 1;
    bool rowok = ((unsigned)rr < 64u);
    const float* row = &g_comb[b][ic][rr * 64];
    float4 f0, f1;
    if (rowok) {
        f0 = *(const float4*)(row + x);
        f1 = *(const float4*)(row + x + 4);
    } else {
        f0 = make_float4(0.f, 0.f, 0.f, 0.f);
        f1 = f0;
    }
    float v[8];
    if (dx == 1) {
        v[0] = f0.x; v[1] = f0.y; v[2] = f0.z; v[3] = f0.w;
        v[4] = f1.x; v[5] = f1.y; v[6] = f1.z; v[7] = f1.w;
    } else if (dx == 0) {
        float L = (rowok && x > 0) ? row[x - 1] : 0.f;
        v[0] = L;    v[1] = f0.x; v[2] = f0.y; v[3] = f0.z;
        v[4] = f0.w; v[5] = f1.x; v[6] = f1.y; v[7] = f1.z;
    } else {
        float R = (rowok && x < 56) ? row[x + 8] : 0.f;
        v[0] = f0.y; v[1] = f0.z; v[2] = f0.w; v[3] = f1.x;
        v[4] = f1.y; v[5] = f1.z; v[6] = f1.w; v[7] = R;
    }
    uint32_t* hp = (uint32_t*)&hi;
    uint32_t* lp = (uint32_t*)&lo;
#pragma unroll
    for (int e2 = 0; e2 < 4; e2++) {
        __nv_bfloat16 h0 = __float2bfloat16(v[2 * e2]);
        __nv_bfloat16 h1 = __float2bfloat16(v[2 * e2 + 1]);
        __nv_bfloat162 hh; hh.x = h0; hh.y = h1;
        __nv_bfloat162 ll;
        ll.x = __float2bfloat16(v[2 * e2] - __bfloat162float(h0));
        ll.y = __float2bfloat16(v[2 * e2 + 1] - __bfloat162float(h1));
        hp[e2] = b2u(hh);
        lp[e2] = b2u(ll);
    }
}

__global__ __launch_bounds__(256, 2) void convgemm_kernel(
    const float* __restrict__ cb)
{
    extern __shared__ char csm[];
    const uint32_t smb = smem_u32(csm);
    const int tid = threadIdx.x, w = tid >> 5, lane = tid & 31;
    const int wp = w & 1, wo = w >> 1;
    const int p0 = blockIdx.x * 128;
    const int o0 = blockIdx.y * 128;
    const int bb_ = blockIdx.x >> 5, pin = p0 & 4095;
    const int pblk = blockIdx.x & 31;

    const int k_it0 = tid >> 4,         seg_it0 = tid & 15;
    const int k_it1 = (256 + tid) >> 4, seg_it1 = tid & 15;

    {
        uint4 hi, lo;
        im2col_tap(k_it0, 0, 0, bb_, pin, seg_it0, hi, lo);
        *(uint4*)(csm + k_it0 * AST + seg_it0 * 16) = hi;
        *(uint4*)(csm + A_BYTES + k_it0 * AST + seg_it0 * 16) = lo;
        im2col_tap(k_it1, 0, 0, bb_, pin, seg_it1, hi, lo);
        *(uint4*)(csm + k_it1 * AST + seg_it1 * 16) = hi;
        *(uint4*)(csm + A_BYTES + k_it1 * AST + seg_it1 * 16) = lo;
        for (int it = 0; it < 4; it++) {
            int flat = it * 256 + tid;
            int v = flat >> 9, rem = flat & 511;
            int o = rem >> 2, seg = rem & 3;
            const __nv_bfloat16* s = (v ? g_Wlo : g_Whi) + (size_t)(o0 + o) * KDIM + seg * 8;
            *(uint4*)(csm + 2 * A_BYTES + v * B_BYTES + o * BST + seg * 16) = *(const uint4*)s;
        }
    }
    __syncthreads();

    float acc[4][4][4];
#pragma unroll
    for (int i = 0; i < 4; i++)
#pragma unroll
        for (int j = 0; j < 4; j++)
#pragma unroll
            for (int e = 0; e < 4; e++) acc[i][j][e] = 0.f;

    const uint32_t arow  = (uint32_t)(((lane >> 4) & 1) * 8 + (lane & 7));
    const uint32_t apcol = (uint32_t)(((lane >> 3) & 1) * 8);
    const uint32_t brow  = (uint32_t)(((lane >> 4) << 3) + (lane & 7));
    const uint32_t bkcs  = (uint32_t)(((lane >> 3) & 1) * 8);

    for (int t = 0; t < 36; t++) {
        const int cur = t & 1;
        const uint32_t Abase = smb + cur * STAGE_BYTES;
        const uint32_t Bbase = Abase + 2 * A_BYTES;
        const bool pf = (t + 1 < 36);

        if (pf) {
            int k0 = (t + 1) * 32;
            uint32_t Bn = smb + (cur ^ 1) * STAGE_BYTES + 2 * A_BYTES;
#pragma unroll
            for (int it = 0; it < 4; it++) {
                int flat = it * 256 + tid;
                int v = flat >> 9, rem = flat & 511;
                int o = rem >> 2, seg = rem & 3;
                cp_async16(Bn + v * B_BYTES + o * BST + seg * 16,
                           (v ? g_Wlo : g_Whi) + (size_t)(o0 + o) * KDIM + k0 + seg * 8);
            }
            CP_COMMIT();
        }

        uint4 pfAh0, pfAl0, pfAh1, pfAl1;
        if (pf) {
            int tn = t + 1;
            int tap = tn >> 2;
            int ic0 = (tn & 3) * 32;
            int dy = tap / 3, dx = tap - dy * 3;
            im2col_tap(ic0 + k_it0, dy, dx, bb_, pin, seg_it0, pfAh0, pfAl0);
            im2col_tap(ic0 + k_it1, dy, dx, bb_, pin, seg_it1, pfAh1, pfAl1);
        }

#pragma unroll
        for (int kf = 0; kf < 2; kf++) {
            uint32_t bh[2][4], bl[2][4];
#pragma unroll
            for (int og = 0; og < 2; og++) {
                uint32_t baddr = Bbase + (wo * 32 + og * 16 + brow) * BST
                               + (kf * 16 + bkcs) * 2;
                ldsm_x4(bh[og][0], bh[og][1], bh[og][2], bh[og][3], baddr);
                ldsm_x4(bl[og][0], bl[og][1], bl[og][2], bl[og][3], baddr + B_BYTES);
            }
#pragma unroll
            for (int mf = 0; mf < 4; mf++) {
                uint32_t aaddr = Abase + (kf * 16 + arow) * AST
                               + (wp * 64 + mf * 16 + apcol) * 2;
                uint32_t ah[4], al[4];
                ldsm_x4_t(ah[0], ah[1], ah[2], ah[3], aaddr);
                ldsm_x4_t(al[0], al[1], al[2], al[3], aaddr + A_BYTES);
#pragma unroll
                for (int og = 0; og < 2; og++) {
                    mma16816(acc[mf][og * 2],     ah, bh[og][0], bh[og][1]);
                    mma16816(acc[mf][og * 2 + 1], ah, bh[og][2], bh[og][3]);
                    mma16816(acc[mf][og * 2],     ah, bl[og][0], bl[og][1]);
                    mma16816(acc[mf][og * 2 + 1], ah, bl[og][2], bl[og][3]);
                    mma16816(acc[mf][og * 2],     al, bh[og][0], bh[og][1]);
                    mma16816(acc[mf][og * 2 + 1], al, bh[og][2], bh[og][3]);
                }
            }
        }

        if (pf) {
            char* stn = csm + (cur ^ 1) * STAGE_BYTES;
            *(uint4*)(stn + k_it0 * AST + seg_it0 * 16) = pfAh0;
            *(uint4*)(stn + A_BYTES + k_it0 * AST + seg_it0 * 16) = pfAl0;
            *(uint4*)(stn + k_it1 * AST + seg_it1 * 16) = pfAh1;
            *(uint4*)(stn + A_BYTES + k_it1 * AST + seg_it1 * 16) = pfAl1;
            CP_WAIT0();
        }
        __syncthreads();
    }

    float* osm = (float*)csm;
    const int prow = wp * 64 + (lane >> 2);
    const int ocol = (lane & 3) * 2;
#pragma unroll
    for (int mf = 0; mf < 4; mf++) {
#pragma unroll
        for (int nf = 0; nf < 4; nf++) {
            int oc = wo * 32 + nf * 8 + ocol;
            int pr = prow + mf * 16;
            osm[oc * 132 + pr]           = acc[mf][nf][0];
            osm[(oc + 1) * 132 + pr]     = acc[mf][nf][1];
            osm[oc * 132 + pr + 8]       = acc[mf][nf][2];
            osm[(oc + 1) * 132 + pr + 8] = acc[mf][nf][3];
        }
    }
    __syncthreads();
#pragma unroll
    for (int it = 0; it < 16; it++) {
        int i = it * 256 + tid;
        int o = i >> 5, seg = i & 31;
        float4 v = *(float4*)&osm[o * 132 + seg * 4];
        float bb = cb[o0 + o];
        v.x += bb; v.y += bb; v.z += bb; v.w += bb;
        *(float4*)&g_y[bb_][o0 + o][pin + seg * 4] = v;
        float s = v.x + v.y + v.z + v.w;
        float q = v.x * v.x + v.y * v.y + v.z * v.z + v.w * v.w;
#pragma unroll
        for (int d = 16; d > 0; d >>= 1) {
            s += __shfl_xor_sync(0xffffffffu, s, d);
            q += __shfl_xor_sync(0xffffffffu, q, d);
        }
        if (lane == 0) {
            g_psum[bb_][pblk][o0 + o]  = s;
            g_psumq[bb_][pblk][o0 + o] = q;
        }
    }
}

// ---------------- GroupNorm finalize ----------------------------------------
__global__ __launch_bounds__(256) void gnfin_kernel()
{
    int idx = blockIdx.x * 256 + threadIdx.x;
    int b = idx >> 8, o = idx & 255;
    float s = 0.f, q = 0.f;
#pragma unroll
    for (int pb = 0; pb < 32; pb++) {
        s += g_psum[b][pb][o];
        q += g_psumq[b][pb][o];
    }
    float mean = s * (1.f / HW);
    float var  = q * (1.f / HW) - mean * mean;
    g_mean[b][o] = mean;
    g_rstd[b][o] = rsqrtf(var + 1e-5f);
}

// ---------------- LSTM gates (float4 vectorized) ----------------------------
__global__ __launch_bounds__(256) void gates_kernel(
    const float* __restrict__ cprev, const float* __restrict__ gnw,
    const float* __restrict__ gnb, float* __restrict__ out)
{
    int idx4 = blockIdx.x * 256 + threadIdx.x;
    int base = idx4 * 4;
    int p  = base & (HW - 1);
    int ch = (base >> 12) & 63;
    int b  = base >> 18;

    float4 yi = *(const float4*)&g_y[b][ch][p];
    float4 yf = *(const float4*)&g_y[b][ch + 64][p];
    float4 yo = *(const float4*)&g_y[b][ch + 128][p];
    float4 yg = *(const float4*)&g_y[b][ch + 192][p];
    float4 cp4 = *(const float4*)&cprev[base];

    float mi = g_mean[b][ch],      ri = g_rstd[b][ch];
    float mf = g_mean[b][ch + 64], rf = g_rstd[b][ch + 64];
    float mo = g_mean[b][ch + 128], ro = g_rstd[b][ch + 128];
    float mg = g_mean[b][ch + 192], rg = g_rstd[b][ch + 192];
    float wi = gnw[ch],       bi_ = gnb[ch];
    float wf = gnw[ch + 64],  bf_ = gnb[ch + 64];
    float wo_ = gnw[ch + 128], bo_ = gnb[ch + 128];
    float wg = gnw[ch + 192], bg_ = gnb[ch + 192];

    float yiv[4] = {yi.x, yi.y, yi.z, yi.w};
    float yfv[4] = {yf.x, yf.y, yf.z, yf.w};
    float yov[4] = {yo.x, yo.y, yo.z, yo.w};
    float ygv[4] = {yg.x, yg.y, yg.z, yg.w};
    float cpv[4] = {cp4.x, cp4.y, cp4.z, cp4.w};
    float hnv[4], cnv[4];
#pragma unroll
    for (int e = 0; e < 4; e++) {
        float ni = (yiv[e] - mi) * ri * wi + bi_;
        float nf = (yfv[e] - mf) * rf * wf + bf_;
        float no_ = (yov[e] - mo) * ro * wo_ + bo_;
        float ng = (ygv[e] - mg) * rg * wg + bg_;
        float ig = 1.f / (1.f + __expf(-ni));
        float fg = 1.f / (1.f + __expf(-nf));
        float og = 1.f / (1.f + __expf(-no_));
        float gg = tanhf(ng);
        float cn = fg * cpv[e] + ig * gg;
        hnv[e] = og * tanhf(cn);
        cnv[e] = cn;
    }
    float4 hn4, cn4;
    hn4.x = hnv[0]; hn4.y = hnv[1]; hn4.z = hnv[2]; hn4.w = hnv[3];
    cn4.x = cnv[0]; cn4.y = cnv[1]; cn4.z = cnv[2]; cn4.w = cnv[3];
    *(float4*)&out[base] = hn4;
    *(float4*)&out[base + BATCH * 64 * HW] = cn4;
}

// ---------------- launch -----------------------------------------------------
extern "C" void kernel_launch(void* const* d_in, const int* in_sizes, int n_in,
                              void* d_out, int out_size)
{
    (void)in_sizes; (void)n_in; (void)out_size;
    const float* x = (const float*)d_in[0];
    const float* h = (const float*)d_in[1];
    const float* c = (const float*)d_in[2];
    const float* aw[2][8];
    for (int a = 0; a < 2; a++)
        for (int j = 0; j < 8; j++)
            aw[a][j] = (const float*)d_in[3 + a * 8 + j];
    const float* conv_w = (const float*)d_in[19];
    const float* conv_b = (const float*)d_in[20];
    const float* gn_w   = (const float*)d_in[21];
    const float* gn_b   = (const float*)d_in[22];
    float* out = (float*)d_out;

    __nv_bfloat16 *bq, *bk, *bv;
    float *z, *comb;
    cudaGetSymbolAddress((void**)&bq, g_bq);
    cudaGetSymbolAddress((void**)&bk, g_bk);
    cudaGetSymbolAddress((void**)&bv, g_bv);
    cudaGetSymbolAddress((void**)&z, g_z);
    cudaGetSymbolAddress((void**)&comb, g_comb);

    cudaFuncSetAttribute(qkv_kernel,
                         cudaFuncAttributeMaxDynamicSharedMemorySize, QKV_SMEM);
    cudaFuncSetAttribute(fproj_kernel,
                         cudaFuncAttributeMaxDynamicSharedMemorySize, FP_SMEM);
    cudaFuncSetAttribute(flash_mma_kernel,
                         cudaFuncAttributeMaxDynamicSharedMemorySize, FL_SMEM);
    cudaFuncSetAttribute(convgemm_kernel,
                         cudaFuncAttributeMaxDynamicSharedMemorySize, CG_SMEM);

    const size_t half = (size_t)BATCH * HW * 64;

    // launch 0: qkv projections + fused conv-weight prep (z == 6)
    QKVp qp;
    qp.src[0] = x; qp.src[1] = h;
    for (int a = 0; a < 2; a++)
        for (int t = 0; t < 3; t++) {
            qp.w[a * 3 + t] = aw[a][2 * t];
            qp.b[a * 3 + t] = aw[a][2 * t + 1];
        }
    qp.dst[0] = bq;        qp.dst[1] = bk;        qp.dst[2] = bv;
    qp.dst[3] = bq + half; qp.dst[4] = bk + half; qp.dst[5] = bv + half;
    qp.cw = conv_w;
    qkv_kernel<<<dim3(64, BATCH, 7), 256, QKV_SMEM>>>(qp);

    // launch 1: flash attention (512 threads, BM=256)
    flash_mma_kernel<<<dim3(16, BATCH, 2), 512, FL_SMEM>>>(bq, bk, bv, z);

    // launch 2
    FPp fp;
    fp.src[0] = x; fp.src[1] = h;
    for (int a = 0; a < 2; a++) { fp.w[a] = aw[a][6]; fp.b[a] = aw[a][7]; }
    fp.z[0] = z; fp.z[1] = z + half;
    fp.comb[0] = comb; fp.comb[1] = comb + (size_t)64 * HW;
    fproj_kernel<<<dim3(64, BATCH, 2), 256, FP_SMEM>>>(fp);

    // launch 3
    convgemm_kernel<<<dim3(NPOS / 128, 2), 256, CG_SMEM>>>(conv_b);

    gnfin_kernel<<<4, 256>>>();
    gates_kernel<<<(BATCH * 64 * HW) / 1024, 256>>>(c, gn_w, gn_b, out);
}

// round 17
// speedup vs baseline: 1.2649x; 1.0995x over previous
#include <cuda_runtime.h>
#include <cuda_bf16.h>
#include <cstdint>

#define HW 4096
#define BATCH 4
#define KDIM 1152
#define NPOS 16384

// ---------------- scratch (device globals) ---------------------------------
__device__ __nv_bfloat16 g_bq[2 * BATCH * HW * 64];
__device__ __nv_bfloat16 g_bk[2 * BATCH * HW * 64];
__device__ __nv_bfloat16 g_bv[2 * BATCH * HW * 64];
__device__ float g_z[2][BATCH][HW * 64];
__device__ float g_comb[BATCH][128][HW];
__device__ float g_y[BATCH][256][HW];
__device__ float g_mean[BATCH][256];
__device__ float g_rstd[BATCH][256];
__device__ float g_psum[BATCH][32][256];
__device__ float g_psumq[BATCH][32][256];
// conv W' permuted: k' = (ky*3+kx)*128 + ic
__device__ __nv_bfloat16 g_Whi[256 * KDIM];
__device__ __nv_bfloat16 g_Wlo[256 * KDIM];
// projection weights hi/lo: [8][64 o][64 k]
__device__ __nv_bfloat16 g_WPhi[8 * 4096];
__device__ __nv_bfloat16 g_WPlo[8 * 4096];

// ---------------- helpers ---------------------------------------------------
__device__ __forceinline__ uint32_t smem_u32(const void* p) {
    uint32_t a;
    asm("{ .reg .u64 t; cvta.to.shared.u64 t, %1; cvt.u32.u64 %0, t; }"
        : "=r"(a) : "l"(p));
    return a;
}
__device__ __forceinline__ void ldsm_x4(uint32_t& r0, uint32_t& r1,
                                        uint32_t& r2, uint32_t& r3, uint32_t a) {
    asm volatile("ldmatrix.sync.aligned.m8n8.x4.shared.b16 {%0,%1,%2,%3}, [%4];"
                 : "=r"(r0), "=r"(r1), "=r"(r2), "=r"(r3) : "r"(a));
}
__device__ __forceinline__ void ldsm_x4_t(uint32_t& r0, uint32_t& r1,
                                          uint32_t& r2, uint32_t& r3, uint32_t a) {
    asm volatile("ldmatrix.sync.aligned.m8n8.x4.trans.shared.b16 {%0,%1,%2,%3}, [%4];"
                 : "=r"(r0), "=r"(r1), "=r"(r2), "=r"(r3) : "r"(a));
}
__device__ __forceinline__ void mma16816(float d[4], const uint32_t a[4],
                                         uint32_t b0, uint32_t b1) {
    asm volatile(
        "mma.sync.aligned.m16n8k16.row.col.f32.bf16.bf16.f32 "
        "{%0,%1,%2,%3},{%4,%5,%6,%7},{%8,%9},{%0,%1,%2,%3};"
        : "+f"(d[0]), "+f"(d[1]), "+f"(d[2]), "+f"(d[3])
        : "r"(a[0]), "r"(a[1]), "r"(a[2]), "r"(a[3]), "r"(b0), "r"(b1));
}
__device__ __forceinline__ uint32_t b2u(__nv_bfloat162 v) {
    return *reinterpret_cast<uint32_t*>(&v);
}
__device__ __forceinline__ void cp_async16(uint32_t dst, const void* src) {
    asm volatile("cp.async.ca.shared.global [%0], [%1], 16;" :: "r"(dst), "l"(src));
}
#define CP_COMMIT() asm volatile("cp.async.commit_group;" ::: "memory")
#define CP_WAIT0()  asm volatile("cp.async.wait_group 0;" ::: "memory")

__device__ __forceinline__ void cvt_pair4(float4 f, uint2& hi, uint2& lo) {
    __nv_bfloat162 h0 = __floats2bfloat162_rn(f.x, f.y);
    __nv_bfloat162 h1 = __floats2bfloat162_rn(f.z, f.w);
    __nv_bfloat162 l0 = __floats2bfloat162_rn(f.x - __bfloat162float(h0.x),
                                              f.y - __bfloat162float(h0.y));
    __nv_bfloat162 l1 = __floats2bfloat162_rn(f.z - __bfloat162float(h1.x),
                                              f.w - __bfloat162float(h1.y));
    hi.x = b2u(h0); hi.y = b2u(h1);
    lo.x = b2u(l0); lo.y = b2u(l1);
}

// ---------------- flash attention: 512 thr, BM=256, 8q x 2k warps ----------
#define QSTR 144
#define QS_OFF 0
#define KS_OFF 36864
#define VS_OFF 55296
#define FL_SMEM 73728

__global__ __launch_bounds__(512, 1) void flash_mma_kernel(
    const __nv_bfloat16* __restrict__ bq, const __nv_bfloat16* __restrict__ bk,
    const __nv_bfloat16* __restrict__ bv, float* __restrict__ gz)
{
    extern __shared__ char smem[];
    const uint32_t smb = smem_u32(smem);
    const int tid = threadIdx.x, w = tid >> 5, lane = tid & 31;
    const int wq = w >> 1, wk = w & 1;
    const int ab = blockIdx.z * BATCH + blockIdx.y;
    const int n0 = blockIdx.x * 256;
    const __nv_bfloat16* qb = bq + (size_t)ab * HW * 64;
    const __nv_bfloat16* kb = bk + (size_t)ab * HW * 64;
    const __nv_bfloat16* vb = bv + (size_t)ab * HW * 64;
    float* zb = gz + (size_t)ab * HW * 64;

    {
        int r = tid >> 1, sg = (tid & 1) * 32;
        const uint4* s = (const uint4*)(qb + (size_t)(n0 + r) * 64 + sg);
        uint4* d = (uint4*)(smem + QS_OFF + r * QSTR + sg * 2);
        d[0] = s[0]; d[1] = s[1]; d[2] = s[2]; d[3] = s[3];
    }
    const int kr = tid >> 3, ksg = (tid & 7) * 8;
    {
        *(uint4*)(smem + KS_OFF + kr * QSTR + ksg * 2) =
            *(const uint4*)(kb + (size_t)kr * 64 + ksg);
        *(uint4*)(smem + VS_OFF + kr * QSTR + ksg * 2) =
            *(const uint4*)(vb + (size_t)kr * 64 + ksg);
    }
    __syncthreads();

    float O[2][8][4];
#pragma unroll
    for (int m = 0; m < 2; m++)
#pragma unroll
        for (int n = 0; n < 8; n++)
#pragma unroll
            for (int e = 0; e < 4; e++) O[m][n][e] = 0.f;
    float rs[2][2] = {{0.f, 0.f}, {0.f, 0.f}};

    const uint32_t aq   = (uint32_t)(((lane >> 3) & 1) * 8 + (lane & 7));
    const uint32_t acol = (uint32_t)((lane >> 4) * 8);
    const uint32_t krow = (uint32_t)(((lane >> 4) << 3) + (lane & 7));
    const uint32_t kcs  = (uint32_t)(((lane >> 3) & 1) * 8);
    const uint32_t vrow = (uint32_t)(((lane >> 3) & 1) * 8 + (lane & 7));
    const uint32_t vcs  = (uint32_t)((lane >> 4) * 8);

    for (int t = 0; t < 64; t++) {
        const int cur = t & 1;
        const uint32_t Kst = smb + KS_OFF + cur * 9216;
        const uint32_t Vst = smb + VS_OFF + cur * 9216;
        const bool pf = (t + 1 < 64);

        if (pf) {
            size_t off = ((size_t)((t + 1) * 64 + kr)) * 64 + ksg;
            cp_async16(smb + KS_OFF + (cur ^ 1) * 9216 + kr * QSTR + ksg * 2,
                       kb + off);
            cp_async16(smb + VS_OFF + (cur ^ 1) * 9216 + kr * QSTR + ksg * 2,
                       vb + off);
            CP_COMMIT();
        }

        float S[2][4][4];
#pragma unroll
        for (int m = 0; m < 2; m++)
#pragma unroll
            for (int n = 0; n < 4; n++)
#pragma unroll
                for (int e = 0; e < 4; e++) S[m][n][e] = 0.f;
#pragma unroll
        for (int ks = 0; ks < 4; ks++) {
            uint32_t qa0[4], qa1[4];
            ldsm_x4(qa0[0], qa0[1], qa0[2], qa0[3],
                    smb + QS_OFF + (wq * 32 + aq) * QSTR + (ks * 16 + acol) * 2);
            ldsm_x4(qa1[0], qa1[1], qa1[2], qa1[3],
                    smb + QS_OFF + (wq * 32 + 16 + aq) * QSTR + (ks * 16 + acol) * 2);
#pragma unroll
            for (int np = 0; np < 2; np++) {
                uint32_t b0, b1, b2, b3;
                ldsm_x4(b0, b1, b2, b3,
                        Kst + (wk * 32 + np * 16 + krow) * QSTR + (ks * 16 + kcs) * 2);
                mma16816(S[0][np * 2],     qa0, b0, b1);
                mma16816(S[0][np * 2 + 1], qa0, b2, b3);
                mma16816(S[1][np * 2],     qa1, b0, b1);
                mma16816(S[1][np * 2 + 1], qa1, b2, b3);
            }
        }

#pragma unroll
        for (int m = 0; m < 2; m++)
#pragma unroll
            for (int n = 0; n < 4; n++) {
                S[m][n][0] = __expf(S[m][n][0]); S[m][n][1] = __expf(S[m][n][1]);
                S[m][n][2] = __expf(S[m][n][2]); S[m][n][3] = __expf(S[m][n][3]);
                rs[m][0] += S[m][n][0] + S[m][n][1];
                rs[m][1] += S[m][n][2] + S[m][n][3];
            }
        uint32_t pa[2][2][4];
#pragma unroll
        for (int kt = 0; kt < 2; kt++)
#pragma unroll
            for (int m = 0; m < 2; m++) {
                pa[kt][m][0] = b2u(__floats2bfloat162_rn(S[m][2*kt][0],   S[m][2*kt][1]));
                pa[kt][m][1] = b2u(__floats2bfloat162_rn(S[m][2*kt][2],   S[m][2*kt][3]));
                pa[kt][m][2] = b2u(__floats2bfloat162_rn(S[m][2*kt+1][0], S[m][2*kt+1][1]));
                pa[kt][m][3] = b2u(__floats2bfloat162_rn(S[m][2*kt+1][2], S[m][2*kt+1][3]));
            }

#pragma unroll
        for (int kt = 0; kt < 2; kt++)
#pragma unroll
            for (int np = 0; np < 4; np++) {
                uint32_t b0, b1, b2, b3;
                ldsm_x4_t(b0, b1, b2, b3,
                          Vst + (wk * 32 + kt * 16 + vrow) * QSTR + (np * 16 + vcs) * 2);
                mma16816(O[0][np * 2],     pa[kt][0], b0, b1);
                mma16816(O[0][np * 2 + 1], pa[kt][0], b2, b3);
                mma16816(O[1][np * 2],     pa[kt][1], b0, b1);
                mma16816(O[1][np * 2 + 1], pa[kt][1], b2, b3);
            }

        if (pf) CP_WAIT0();
        __syncthreads();
    }

#pragma unroll
    for (int m = 0; m < 2; m++)
#pragma unroll
        for (int j = 0; j < 2; j++) {
            rs[m][j] += __shfl_xor_sync(0xffffffffu, rs[m][j], 1);
            rs[m][j] += __shfl_xor_sync(0xffffffffu, rs[m][j], 2);
        }

    float* osm = (float*)smem;
    float* lsm = (float*)(smem + KS_OFF);
    const int rl = wq * 16 + (lane >> 2);
    const int cb = (lane & 3) * 2;
#pragma unroll
    for (int m = 0; m < 2; m++) {
        __syncthreads();
        if (wk == 1) {
#pragma unroll
            for (int nf = 0; nf < 8; nf++) {
                int c = nf * 8 + cb;
                osm[rl * 68 + c]           = O[m][nf][0];
                osm[rl * 68 + c + 1]       = O[m][nf][1];
                osm[(rl + 8) * 68 + c]     = O[m][nf][2];
                osm[(rl + 8) * 68 + c + 1] = O[m][nf][3];
            }
            if ((lane & 3) == 0) {
                lsm[rl] = rs[m][0];
                lsm[rl + 8] = rs[m][1];
            }
        }
        __syncthreads();
        if (wk == 0) {
#pragma unroll
            for (int nf = 0; nf < 8; nf++) {
                int c = nf * 8 + cb;
                O[m][nf][0] += osm[rl * 68 + c];
                O[m][nf][1] += osm[rl * 68 + c + 1];
                O[m][nf][2] += osm[(rl + 8) * 68 + c];
                O[m][nf][3] += osm[(rl + 8) * 68 + c + 1];
            }
            rs[m][0] += lsm[rl];
            rs[m][1] += lsm[rl + 8];
        }
    }

    if (wk == 0) {
#pragma unroll
        for (int m = 0; m < 2; m++) {
            float ia = 1.f / rs[m][0], ib = 1.f / rs[m][1];
            int ra = n0 + wq * 32 + m * 16 + (lane >> 2);
            int rb = ra + 8;
#pragma unroll
            for (int nf = 0; nf < 8; nf++) {
                int c = nf * 8 + cb;
                float2 va; va.x = O[m][nf][0] * ia; va.y = O[m][nf][1] * ia;
                float2 vv; vv.x = O[m][nf][2] * ib; vv.y = O[m][nf][3] * ib;
                *(float2*)&zb[(size_t)ra * 64 + c] = va;
                *(float2*)&zb[(size_t)rb * 64 + c] = vv;
            }
        }
    }
}

// ---------------- weight prep: conv (permuted) + 8 projection mats ----------
struct WPp {
    const float* cw;
    const float* pw[8];
};
__global__ __launch_bounds__(256) void wprep_kernel(WPp P)
{
    int bx = blockIdx.x;
    if (bx < 256) {
        int o = bx;
        for (int kp = threadIdx.x; kp < KDIM; kp += 256) {
            int tap = kp >> 7, ic = kp & 127;
            float v = P.cw[(size_t)o * KDIM + ic * 9 + tap];
            __nv_bfloat16 h = __float2bfloat16(v);
            __nv_bfloat16 l = __float2bfloat16(v - __bfloat162float(h));
            g_Whi[(size_t)o * KDIM + kp] = h;
            g_Wlo[(size_t)o * KDIM + kp] = l;
        }
    } else {
        int j = bx - 256;
        const float* w = P.pw[j];
        for (int idx = threadIdx.x; idx < 4096; idx += 256) {
            float v = w[idx];           // [o][i] row-major = [o][k]
            __nv_bfloat16 h = __float2bfloat16(v);
            __nv_bfloat16 l = __float2bfloat16(v - __bfloat162float(h));
            g_WPhi[j * 4096 + idx] = h;
            g_WPlo[j * 4096 + idx] = l;
        }
    }
}

// ---------------- projection GEMMs on mma.sync (128p x 64o, K=64) ----------
#define PAST 272
#define PA_BYTES (64 * PAST)
#define PB_OFF   (2 * PA_BYTES)
#define PBST 144
#define PB_BYTES (64 * PBST)
#define PG_SMEM  (PB_OFF + 2 * PB_BYTES)

// shared GEMM core: A hi/lo in smem[0 / PA_BYTES], B hi/lo at PB_OFF.
// acc[mf][nf][4]: p rows wp*64+mf*16, o cols wo*16+nf*8.
__device__ __forceinline__ void proj_core(uint32_t smb, int w, int lane,
                                          float acc[4][2][4]) {
    const int wp = w & 1, wo = w >> 1;
    const uint32_t arow  = (uint32_t)(((lane >> 4) & 1) * 8 + (lane & 7));
    const uint32_t apcol = (uint32_t)(((lane >> 3) & 1) * 8);
    const uint32_t brow  = (uint32_t)(((lane >> 4) << 3) + (lane & 7));
    const uint32_t bkcs  = (uint32_t)(((lane >> 3) & 1) * 8);
#pragma unroll
    for (int kf = 0; kf < 4; kf++) {
        uint32_t bh0, bh1, bh2, bh3, bl0, bl1, bl2, bl3;
        uint32_t baddr = smb + PB_OFF + (wo * 16 + brow) * PBST
                       + (kf * 16 + bkcs) * 2;
        ldsm_x4(bh0, bh1, bh2, bh3, baddr);
        ldsm_x4(bl0, bl1, bl2, bl3, baddr + PB_BYTES);
#pragma unroll
        for (int mf = 0; mf < 4; mf++) {
            uint32_t aaddr = smb + (kf * 16 + arow) * PAST
                           + (wp * 64 + mf * 16 + apcol) * 2;
            uint32_t ah[4], al[4];
            ldsm_x4_t(ah[0], ah[1], ah[2], ah[3], aaddr);
            ldsm_x4_t(al[0], al[1], al[2], al[3], aaddr + PA_BYTES);
            mma16816(acc[mf][0], ah, bh0, bh1);
            mma16816(acc[mf][1], ah, bh2, bh3);
            mma16816(acc[mf][0], ah, bl0, bl1);
            mma16816(acc[mf][1], ah, bl2, bl3);
            mma16816(acc[mf][0], al, bh0, bh1);
            mma16816(acc[mf][1], al, bh2, bh3);
        }
    }
}

__device__ __forceinline__ void proj_loadB(char* smem, int tid, int slot) {
    const __nv_bfloat16* wh = g_WPhi + slot * 4096;
    const __nv_bfloat16* wl = g_WPlo + slot * 4096;
#pragma unroll
    for (int it = 0; it < 2; it++) {
        int flat = it * 256 + tid;
        int o = flat >> 3, seg = flat & 7;
        *(uint4*)(smem + PB_OFF + o * PBST + seg * 16) =
            *(const uint4*)(wh + o * 64 + seg * 8);
        *(uint4*)(smem + PB_OFF + PB_BYTES + o * PBST + seg * 16) =
            *(const uint4*)(wl + o * 64 + seg * 8);
    }
}

__device__ __forceinline__ void proj_stage(float* osm, int w, int lane,
                                           float acc[4][2][4]) {
    const int wp = w & 1, wo = w >> 1;
    const int prow = wp * 64 + (lane >> 2);
    const int ocol = (lane & 3) * 2;
#pragma unroll
    for (int mf = 0; mf < 4; mf++)
#pragma unroll
        for (int nf = 0; nf < 2; nf++) {
            int oc = wo * 16 + nf * 8 + ocol;
            int pr = prow + mf * 16;
            osm[oc * 132 + pr]           = acc[mf][nf][0];
            osm[(oc + 1) * 132 + pr]     = acc[mf][nf][1];
            osm[oc * 132 + pr + 8]       = acc[mf][nf][2];
            osm[(oc + 1) * 132 + pr + 8] = acc[mf][nf][3];
        }
}

// qkv: grid (32 ptiles, BATCH, 6)
struct QGp {
    const float* src[2];
    const float* bias[6];
    __nv_bfloat16* dst[6];
};
__global__ __launch_bounds__(256) void qkvg_kernel(QGp P)
{
    extern __shared__ char psm[];
    const uint32_t smb = smem_u32(psm);
    const int tid = threadIdx.x, w = tid >> 5, lane = tid & 31;
    const int z = blockIdx.z, b = blockIdx.y, p0 = blockIdx.x * 128;
    const float* inB = P.src[z / 3] + (size_t)b * 64 * HW;
    const float* bias = P.bias[z];
    __nv_bfloat16* outB = P.dst[z] + (size_t)b * HW * 64;

    // A tile: rows k=i (64), cols p (128), hi/lo
    {
        int row = tid >> 2, sg = (tid & 3) * 32;
        const float* src = inB + (size_t)row * HW + p0 + sg;
        uint32_t da = (uint32_t)(row * PAST + sg * 2);
#pragma unroll
        for (int e = 0; e < 8; e++) {
            float4 f = *(const float4*)(src + e * 4);
            uint2 hi, lo;
            cvt_pair4(f, hi, lo);
            *(uint2*)(psm + da + e * 8) = hi;
            *(uint2*)(psm + PA_BYTES + da + e * 8) = lo;
        }
    }
    proj_loadB(psm, tid, z);
    __syncthreads();

    float acc[4][2][4];
#pragma unroll
    for (int i = 0; i < 4; i++)
#pragma unroll
        for (int j = 0; j < 2; j++)
#pragma unroll
            for (int e = 0; e < 4; e++) acc[i][j][e] = 0.f;
    proj_core(smb, w, lane, acc);

    __syncthreads();
    float* osm = (float*)psm;
    proj_stage(osm, w, lane, acc);
    __syncthreads();

    // write bf16 [p][64 o]
#pragma unroll
    for (int it = 0; it < 8; it++) {
        int item = it * 256 + tid;
        int p = item >> 4, q = item & 15;
        int o0 = q * 4;
        float v0 = osm[(o0 + 0) * 132 + p] + bias[o0 + 0];
        float v1 = osm[(o0 + 1) * 132 + p] + bias[o0 + 1];
        float v2 = osm[(o0 + 2) * 132 + p] + bias[o0 + 2];
        float v3 = osm[(o0 + 3) * 132 + p] + bias[o0 + 3];
        uint2 u;
        u.x = b2u(__floats2bfloat162_rn(v0, v1));
        u.y = b2u(__floats2bfloat162_rn(v2, v3));
        *(uint2*)&outB[(size_t)(p0 + p) * 64 + o0] = u;
    }
}

// fproj: grid (32 ptiles, BATCH, 2)
struct FGp {
    const float* src[2];
    const float* zbuf[2];
    const float* bias[2];
    float* out[2];
};
__global__ __launch_bounds__(256) void fprojg_kernel(FGp P)
{
    extern __shared__ char psm[];
    const uint32_t smb = smem_u32(psm);
    const int tid = threadIdx.x, w = tid >> 5, lane = tid & 31;
    const int a2 = blockIdx.z, b = blockIdx.y, p0 = blockIdx.x * 128;
    const float* inB = P.src[a2] + (size_t)b * 64 * HW;
    const float* zB  = P.zbuf[a2] + (size_t)b * HW * 64;
    const float* bias = P.bias[a2];
    float* outF = P.out[a2] + (size_t)b * 128 * HW;

    // A tile: (z*x)[i][p] hi/lo
    {
        int row = tid >> 2, sg = (tid & 3) * 32;
        const float* sx = inB + (size_t)row * HW + p0 + sg;
        const float* sz = zB + (size_t)row * HW + p0 + sg;
        uint32_t da = (uint32_t)(row * PAST + sg * 2);
#pragma unroll
        for (int e = 0; e < 8; e++) {
            float4 fx = *(const float4*)(sx + e * 4);
            float4 fz = *(const float4*)(sz + e * 4);
            float4 f;
            f.x = fx.x * fz.x; f.y = fx.y * fz.y;
            f.z = fx.z * fz.z; f.w = fx.w * fz.w;
            uint2 hi, lo;
            cvt_pair4(f, hi, lo);
            *(uint2*)(psm + da + e * 8) = hi;
            *(uint2*)(psm + PA_BYTES + da + e * 8) = lo;
        }
    }
    proj_loadB(psm, tid, 6 + a2);
    __syncthreads();

    float acc[4][2][4];
#pragma unroll
    for (int i = 0; i < 4; i++)
#pragma unroll
        for (int j = 0; j < 2; j++)
#pragma unroll
            for (int e = 0; e < 4; e++) acc[i][j][e] = 0.f;
    proj_core(smb, w, lane, acc);

    __syncthreads();
    float* osm = (float*)psm;
    proj_stage(osm, w, lane, acc);
    __syncthreads();

    // write fp32 [o][HW] with bias + residual
#pragma unroll
    for (int it = 0; it < 8; it++) {
        int i = it * 256 + tid;
        int o = i >> 5, seg = i & 31;
        float4 v = *(float4*)&osm[o * 132 + seg * 4];
        float bb = bias[o];
        float4 r = *(const float4*)&inB[(size_t)o * HW + p0 + seg * 4];
        v.x += bb + r.x; v.y += bb + r.y;
        v.z += bb + r.z; v.w += bb + r.w;
        *(float4*)&outF[(size_t)o * HW + p0 + seg * 4] = v;
    }
}

// ---------------- conv as GEMM: tap-major K, uniform-shift im2col -----------
#define AST 272
#define BST 80
#define A_BYTES (32 * AST)
#define B_BYTES (128 * BST)
#define STAGE_BYTES (2 * A_BYTES + 2 * B_BYTES)
#define CG_SMEM (2 * STAGE_BYTES)

__device__ __forceinline__ void im2col_tap(int ic, int dy, int dx, int b,
                                           int pin, int seg,
                                           uint4& hi, uint4& lo) {
    int p = pin + seg * 8;
    int r = p >> 6, x = p & 63;
    int rr = r + dy - 1;
    bool rowok = ((unsigned)rr < 64u);
    const float* row = &g_comb[b][ic][rr * 64];
    float4 f0, f1;
    if (rowok) {
        f0 = *(const float4*)(row + x);
        f1 = *(const float4*)(row + x + 4);
    } else {
        f0 = make_float4(0.f, 0.f, 0.f, 0.f);
        f1 = f0;
    }
    float v[8];
    if (dx == 1) {
        v[0] = f0.x; v[1] = f0.y; v[2] = f0.z; v[3] = f0.w;
        v[4] = f1.x; v[5] = f1.y; v[6] = f1.z; v[7] = f1.w;
    } else if (dx == 0) {
        float L = (rowok && x > 0) ? row[x - 1] : 0.f;
        v[0] = L;    v[1] = f0.x; v[2] = f0.y; v[3] = f0.z;
        v[4] = f0.w; v[5] = f1.x; v[6] = f1.y; v[7] = f1.z;
    } else {
        float R = (rowok && x < 56) ? row[x + 8] : 0.f;
        v[0] = f0.y; v[1] = f0.z; v[2] = f0.w; v[3] = f1.x;
        v[4] = f1.y; v[5] = f1.z; v[6] = f1.w; v[7] = R;
    }
    uint32_t* hp = (uint32_t*)&hi;
    uint32_t* lp = (uint32_t*)&lo;
#pragma unroll
    for (int e2 = 0; e2 < 4; e2++) {
        __nv_bfloat16 h0 = __float2bfloat16(v[2 * e2]);
        __nv_bfloat16 h1 = __float2bfloat16(v[2 * e2 + 1]);
        __nv_bfloat162 hh; hh.x = h0; hh.y = h1;
        __nv_bfloat162 ll;
        ll.x = __float2bfloat16(v[2 * e2] - __bfloat162float(h0));
        ll.y = __float2bfloat16(v[2 * e2 + 1] - __bfloat162float(h1));
        hp[e2] = b2u(hh);
        lp[e2] = b2u(ll);
    }
}

__global__ __launch_bounds__(256, 2) void convgemm_kernel(
    const float* __restrict__ cb)
{
    extern __shared__ char csm[];
    const uint32_t smb = smem_u32(csm);
    const int tid = threadIdx.x, w = tid >> 5, lane = tid & 31;
    const int wp = w & 1, wo = w >> 1;
    const int p0 = blockIdx.x * 128;
    const int o0 = blockIdx.y * 128;
    const int bb_ = blockIdx.x >> 5, pin = p0 & 4095;
    const int pblk = blockIdx.x & 31;

    const int k_it0 = tid >> 4,         seg_it0 = tid & 15;
    const int k_it1 = (256 + tid) >> 4, seg_it1 = tid & 15;

    {
        uint4 hi, lo;
        im2col_tap(k_it0, 0, 0, bb_, pin, seg_it0, hi, lo);
        *(uint4*)(csm + k_it0 * AST + seg_it0 * 16) = hi;
        *(uint4*)(csm + A_BYTES + k_it0 * AST + seg_it0 * 16) = lo;
        im2col_tap(k_it1, 0, 0, bb_, pin, seg_it1, hi, lo);
        *(uint4*)(csm + k_it1 * AST + seg_it1 * 16) = hi;
        *(uint4*)(csm + A_BYTES + k_it1 * AST + seg_it1 * 16) = lo;
        for (int it = 0; it < 4; it++) {
            int flat = it * 256 + tid;
            int v = flat >> 9, rem = flat & 511;
            int o = rem >> 2, seg = rem & 3;
            const __nv_bfloat16* s = (v ? g_Wlo : g_Whi) + (size_t)(o0 + o) * KDIM + seg * 8;
            *(uint4*)(csm + 2 * A_BYTES + v * B_BYTES + o * BST + seg * 16) = *(const uint4*)s;
        }
    }
    __syncthreads();

    float acc[4][4][4];
#pragma unroll
    for (int i = 0; i < 4; i++)
#pragma unroll
        for (int j = 0; j < 4; j++)
#pragma unroll
            for (int e = 0; e < 4; e++) acc[i][j][e] = 0.f;

    const uint32_t arow  = (uint32_t)(((lane >> 4) & 1) * 8 + (lane & 7));
    const uint32_t apcol = (uint32_t)(((lane >> 3) & 1) * 8);
    const uint32_t brow  = (uint32_t)(((lane >> 4) << 3) + (lane & 7));
    const uint32_t bkcs  = (uint32_t)(((lane >> 3) & 1) * 8);

    for (int t = 0; t < 36; t++) {
        const int cur = t & 1;
        const uint32_t Abase = smb + cur * STAGE_BYTES;
        const uint32_t Bbase = Abase + 2 * A_BYTES;
        const bool pf = (t + 1 < 36);

        if (pf) {
            int k0 = (t + 1) * 32;
            uint32_t Bn = smb + (cur ^ 1) * STAGE_BYTES + 2 * A_BYTES;
#pragma unroll
            for (int it = 0; it < 4; it++) {
                int flat = it * 256 + tid;
                int v = flat >> 9, rem = flat & 511;
                int o = rem >> 2, seg = rem & 3;
                cp_async16(Bn + v * B_BYTES + o * BST + seg * 16,
                           (v ? g_Wlo : g_Whi) + (size_t)(o0 + o) * KDIM + k0 + seg * 8);
            }
            CP_COMMIT();
        }

        uint4 pfAh0, pfAl0, pfAh1, pfAl1;
        if (pf) {
            int tn = t + 1;
            int tap = tn >> 2;
            int ic0 = (tn & 3) * 32;
            int dy = tap / 3, dx = tap - dy * 3;
            im2col_tap(ic0 + k_it0, dy, dx, bb_, pin, seg_it0, pfAh0, pfAl0);
            im2col_tap(ic0 + k_it1, dy, dx, bb_, pin, seg_it1, pfAh1, pfAl1);
        }

#pragma unroll
        for (int kf = 0; kf < 2; kf++) {
            uint32_t bh[2][4], bl[2][4];
#pragma unroll
            for (int og = 0; og < 2; og++) {
                uint32_t baddr = Bbase + (wo * 32 + og * 16 + brow) * BST
                               + (kf * 16 + bkcs) * 2;
                ldsm_x4(bh[og][0], bh[og][1], bh[og][2], bh[og][3], baddr);
                ldsm_x4(bl[og][0], bl[og][1], bl[og][2], bl[og][3], baddr + B_BYTES);
            }
#pragma unroll
            for (int mf = 0; mf < 4; mf++) {
                uint32_t aaddr = Abase + (kf * 16 + arow) * AST
                               + (wp * 64 + mf * 16 + apcol) * 2;
                uint32_t ah[4], al[4];
                ldsm_x4_t(ah[0], ah[1], ah[2], ah[3], aaddr);
                ldsm_x4_t(al[0], al[1], al[2], al[3], aaddr + A_BYTES);
#pragma unroll
                for (int og = 0; og < 2; og++) {
                    mma16816(acc[mf][og * 2],     ah, bh[og][0], bh[og][1]);
                    mma16816(acc[mf][og * 2 + 1], ah, bh[og][2], bh[og][3]);
                    mma16816(acc[mf][og * 2],     ah, bl[og][0], bl[og][1]);
                    mma16816(acc[mf][og * 2 + 1], ah, bl[og][2], bl[og][3]);
                    mma16816(acc[mf][og * 2],     al, bh[og][0], bh[og][1]);
                    mma16816(acc[mf][og * 2 + 1], al, bh[og][2], bh[og][3]);
                }
            }
        }

        if (pf) {
            char* stn = csm + (cur ^ 1) * STAGE_BYTES;
            *(uint4*)(stn + k_it0 * AST + seg_it0 * 16) = pfAh0;
            *(uint4*)(stn + A_BYTES + k_it0 * AST + seg_it0 * 16) = pfAl0;
            *(uint4*)(stn + k_it1 * AST + seg_it1 * 16) = pfAh1;
            *(uint4*)(stn + A_BYTES + k_it1 * AST + seg_it1 * 16) = pfAl1;
            CP_WAIT0();
        }
        __syncthreads();
    }

    float* osm = (float*)csm;
    const int prow = wp * 64 + (lane >> 2);
    const int ocol = (lane & 3) * 2;
#pragma unroll
    for (int mf = 0; mf < 4; mf++) {
#pragma unroll
        for (int nf = 0; nf < 4; nf++) {
            int oc = wo * 32 + nf * 8 + ocol;
            int pr = prow + mf * 16;
            osm[oc * 132 + pr]           = acc[mf][nf][0];
            osm[(oc + 1) * 132 + pr]     = acc[mf][nf][1];
            osm[oc * 132 + pr + 8]       = acc[mf][nf][2];
            osm[(oc + 1) * 132 + pr + 8] = acc[mf][nf][3];
        }
    }
    __syncthreads();
#pragma unroll
    for (int it = 0; it < 16; it++) {
        int i = it * 256 + tid;
        int o = i >> 5, seg = i & 31;
        float4 v = *(float4*)&osm[o * 132 + seg * 4];
        float bb = cb[o0 + o];
        v.x += bb; v.y += bb; v.z += bb; v.w += bb;
        *(float4*)&g_y[bb_][o0 + o][pin + seg * 4] = v;
        float s = v.x + v.y + v.z + v.w;
        float q = v.x * v.x + v.y * v.y + v.z * v.z + v.w * v.w;
#pragma unroll
        for (int d = 16; d > 0; d >>= 1) {
            s += __shfl_xor_sync(0xffffffffu, s, d);
            q += __shfl_xor_sync(0xffffffffu, q, d);
        }
        if (lane == 0) {
            g_psum[bb_][pblk][o0 + o]  = s;
            g_psumq[bb_][pblk][o0 + o] = q;
        }
    }
}

// ---------------- GroupNorm finalize ----------------------------------------
__global__ __launch_bounds__(256) void gnfin_kernel()
{
    int idx = blockIdx.x * 256 + threadIdx.x;
    int b = idx >> 8, o = idx & 255;
    float s = 0.f, q = 0.f;
#pragma unroll
    for (int pb = 0; pb < 32; pb++) {
        s += g_psum[b][pb][o];
        q += g_psumq[b][pb][o];
    }
    float mean = s * (1.f / HW);
    float var  = q * (1.f / HW) - mean * mean;
    g_mean[b][o] = mean;
    g_rstd[b][o] = rsqrtf(var + 1e-5f);
}

// ---------------- LSTM gates (float4 vectorized) ----------------------------
__global__ __launch_bounds__(256) void gates_kernel(
    const float* __restrict__ cprev, const float* __restrict__ gnw,
    const float* __restrict__ gnb, float* __restrict__ out)
{
    int idx4 = blockIdx.x * 256 + threadIdx.x;
    int base = idx4 * 4;
    int p  = base & (HW - 1);
    int ch = (base >> 12) & 63;
    int b  = base >> 18;

    float4 yi = *(const float4*)&g_y[b][ch][p];
    float4 yf = *(const float4*)&g_y[b][ch + 64][p];
    float4 yo = *(const float4*)&g_y[b][ch + 128][p];
    float4 yg = *(const float4*)&g_y[b][ch + 192][p];
    float4 cp4 = *(const float4*)&cprev[base];

    float mi = g_mean[b][ch],      ri = g_rstd[b][ch];
    float mf = g_mean[b][ch + 64], rf = g_rstd[b][ch + 64];
    float mo = g_mean[b][ch + 128], ro = g_rstd[b][ch + 128];
    float mg = g_mean[b][ch + 192], rg = g_rstd[b][ch + 192];
    float wi = gnw[ch],       bi_ = gnb[ch];
    float wf = gnw[ch + 64],  bf_ = gnb[ch + 64];
    float wo_ = gnw[ch + 128], bo_ = gnb[ch + 128];
    float wg = gnw[ch + 192], bg_ = gnb[ch + 192];

    float yiv[4] = {yi.x, yi.y, yi.z, yi.w};
    float yfv[4] = {yf.x, yf.y, yf.z, yf.w};
    float yov[4] = {yo.x, yo.y, yo.z, yo.w};
    float ygv[4] = {yg.x, yg.y, yg.z, yg.w};
    float cpv[4] = {cp4.x, cp4.y, cp4.z, cp4.w};
    float hnv[4], cnv[4];
#pragma unroll
    for (int e = 0; e < 4; e++) {
        float ni = (yiv[e] - mi) * ri * wi + bi_;
        float nf = (yfv[e] - mf) * rf * wf + bf_;
        float no_ = (yov[e] - mo) * ro * wo_ + bo_;
        float ng = (ygv[e] - mg) * rg * wg + bg_;
        float ig = 1.f / (1.f + __expf(-ni));
        float fg = 1.f / (1.f + __expf(-nf));
        float og = 1.f / (1.f + __expf(-no_));
        float gg = tanhf(ng);
        float cn = fg * cpv[e] + ig * gg;
        hnv[e] = og * tanhf(cn);
        cnv[e] = cn;
    }
    float4 hn4, cn4;
    hn4.x = hnv[0]; hn4.y = hnv[1]; hn4.z = hnv[2]; hn4.w = hnv[3];
    cn4.x = cnv[0]; cn4.y = cnv[1]; cn4.z = cnv[2]; cn4.w = cnv[3];
    *(float4*)&out[base] = hn4;
    *(float4*)&out[base + BATCH * 64 * HW] = cn4;
}

// ---------------- launch -----------------------------------------------------
extern "C" void kernel_launch(void* const* d_in, const int* in_sizes, int n_in,
                              void* d_out, int out_size)
{
    (void)in_sizes; (void)n_in; (void)out_size;
    const float* x = (const float*)d_in[0];
    const float* h = (const float*)d_in[1];
    const float* c = (const float*)d_in[2];
    const float* aw[2][8];
    for (int a = 0; a < 2; a++)
        for (int j = 0; j < 8; j++)
            aw[a][j] = (const float*)d_in[3 + a * 8 + j];
    const float* conv_w = (const float*)d_in[19];
    const float* conv_b = (const float*)d_in[20];
    const float* gn_w   = (const float*)d_in[21];
    const float* gn_b   = (const float*)d_in[22];
    float* out = (float*)d_out;

    __nv_bfloat16 *bq, *bk, *bv;
    float *z, *comb;
    cudaGetSymbolAddress((void**)&bq, g_bq);
    cudaGetSymbolAddress((void**)&bk, g_bk);
    cudaGetSymbolAddress((void**)&bv, g_bv);
    cudaGetSymbolAddress((void**)&z, g_z);
    cudaGetSymbolAddress((void**)&comb, g_comb);

    cudaFuncSetAttribute(qkvg_kernel,
                         cudaFuncAttributeMaxDynamicSharedMemorySize, PG_SMEM);
    cudaFuncSetAttribute(fprojg_kernel,
                         cudaFuncAttributeMaxDynamicSharedMemorySize, PG_SMEM);
    cudaFuncSetAttribute(flash_mma_kernel,
                         cudaFuncAttributeMaxDynamicSharedMemorySize, FL_SMEM);
    cudaFuncSetAttribute(convgemm_kernel,
                         cudaFuncAttributeMaxDynamicSharedMemorySize, CG_SMEM);

    const size_t half = (size_t)BATCH * HW * 64;

    // launch 0: all weight prep (conv + 8 projection matrices)
    WPp wp;
    wp.cw = conv_w;
    for (int a = 0; a < 2; a++)
        for (int t = 0; t < 3; t++)
            wp.pw[a * 3 + t] = aw[a][2 * t];
    wp.pw[6] = aw[0][6];
    wp.pw[7] = aw[1][6];
    wprep_kernel<<<264, 256>>>(wp);

    // launch 1: q/k/v projections on tensor cores
    QGp qg;
    qg.src[0] = x; qg.src[1] = h;
    for (int a = 0; a < 2; a++)
        for (int t = 0; t < 3; t++)
            qg.bias[a * 3 + t] = aw[a][2 * t + 1];
    qg.dst[0] = bq;        qg.dst[1] = bk;        qg.dst[2] = bv;
    qg.dst[3] = bq + half; qg.dst[4] = bk + half; qg.dst[5] = bv + half;
    qkvg_kernel<<<dim3(32, BATCH, 6), 256, PG_SMEM>>>(qg);

    // launch 2: flash attention (512 threads, BM=256)
    flash_mma_kernel<<<dim3(16, BATCH, 2), 512, FL_SMEM>>>(bq, bk, bv, z);

    // launch 3 (ncu-profiled slot): f-projection on tensor cores
    FGp fg;
    fg.src[0] = x; fg.src[1] = h;
    fg.zbuf[0] = z; fg.zbuf[1] = z + half;
    fg.bias[0] = aw[0][7]; fg.bias[1] = aw[1][7];
    fg.out[0] = comb; fg.out[1] = comb + (size_t)64 * HW;
    fprojg_kernel<<<dim3(32, BATCH, 2), 256, PG_SMEM>>>(fg);

    convgemm_kernel<<<dim3(NPOS / 128, 2), 256, CG_SMEM>>>(conv_b);
    gnfin_kernel<<<4, 256>>>();
    gates_kernel<<<(BATCH * 64 * HW) / 1024, 256>>>(c, gn_w, gn_b, out);
}